// round 14
// baseline (speedup 1.0000x reference)
#include <cuda_runtime.h>
#include <cstdint>
#include <math.h>

#define NN 4
#define CC 512
#define DD 768
#define HH 12
#define EE 20
#define MMENT 4
#define PP 380
#define NP 1520
#define LL 97
#define DIM2 1536
#define DIM3 2304
#define DIM4 3072
#define KBIL 49152
#define NEGV (-1e30f)

// ---------------- static device scratch ----------------
__device__ float g_eemb[NN*EE*MMENT*DD];
__device__ float g_eatt[NN*EE*MMENT*CC];
__device__ float g_glob[NN*EE*DD];
__device__ float g_A[NN*EE*DD];
__device__ float g_B[NN*EE*DD];
__device__ float g_edge[NN*EE*EE*DD];
__device__ float g_pa[NP*CC];
__device__ float g_qW[NP*DIM4];
__device__ float g_hs[NP*DD];
__device__ float g_ts[NP*DD];
__device__ float g_part[4*NP*DD];
__device__ float g_spart[4*NP*EE];
__device__ float g_aw[NP*EE];
// tf32 (u32 bit pattern) GEMM operands
__device__ uint32_t g_pa32[NP*CC];
__device__ uint32_t g_seqT32[NN*DD*CC];
__device__ uint32_t g_q32[NP*DIM2];
__device__ uint32_t g_hcat32[NP*DIM3];
__device__ uint32_t g_tcat32[NP*DIM3];
__device__ uint32_t g_praw32[NP*DIM4];
__device__ uint32_t g_wT_att32[DIM4*DIM2];
__device__ uint32_t g_wT_path32[DD*DIM4];
__device__ uint32_t g_wT_head32[DD*DIM3];
__device__ uint32_t g_wT_tail32[DD*DIM3];
__device__ uint32_t g_wT_bil32[128*KBIL];   // rows 97..127 zero

// ---------------- helpers ----------------
__device__ __forceinline__ uint32_t f2tf32(float f) {
    uint32_t r;
    asm("cvt.rna.tf32.f32 %0, %1;" : "=r"(r) : "f"(f));
    return r;
}
__device__ __forceinline__ void mma_tf32(float* d, uint32_t a0, uint32_t a1,
                                         uint32_t a2, uint32_t a3,
                                         uint32_t b0, uint32_t b1)
{
    asm volatile(
        "mma.sync.aligned.m16n8k8.row.col.f32.tf32.tf32.f32 "
        "{%0,%1,%2,%3}, {%4,%5,%6,%7}, {%8,%9}, {%0,%1,%2,%3};"
        : "+f"(d[0]), "+f"(d[1]), "+f"(d[2]), "+f"(d[3])
        : "r"(a0), "r"(a1), "r"(a2), "r"(a3), "r"(b0), "r"(b1));
}
__device__ __forceinline__ void ldsm4(uint32_t addr, uint32_t& a, uint32_t& b,
                                      uint32_t& c, uint32_t& d)
{
    asm volatile("ldmatrix.sync.aligned.m8n8.x4.shared.b16 {%0,%1,%2,%3}, [%4];"
                 : "=r"(a), "=r"(b), "=r"(c), "=r"(d) : "r"(addr));
}
__device__ __forceinline__ void sts128(uint32_t addr, uint32_t x, uint32_t y,
                                       uint32_t z, uint32_t w)
{
    asm volatile("st.shared.v4.b32 [%0], {%1,%2,%3,%4};"
                 :: "r"(addr), "r"(x), "r"(y), "r"(z), "r"(w) : "memory");
}
__device__ __forceinline__ void cpa16(uint32_t dst, const void* src, uint32_t sz)
{
    asm volatile("cp.async.cg.shared.global [%0], [%1], 16, %2;"
                 :: "r"(dst), "l"(src), "r"(sz) : "memory");
}
#define CP_COMMIT() asm volatile("cp.async.commit_group;" ::: "memory")
#define CP_WAIT0()  asm volatile("cp.async.wait_group 0;" ::: "memory")
#define CP_WAIT1()  asm volatile("cp.async.wait_group 1;" ::: "memory")

// pair-index helper: global pair id for group member jj (0..18) in doc n, entity e
__device__ __forceinline__ int group_pair(int n, int e, int jj, bool grouph)
{
    if (grouph) return n*PP + e*19 + jj;
    int i = jj + (jj >= e);
    return n*PP + i*19 + (e < i ? e : e - 1);
}

// ================ tf32 warp-mma GEMM: 3-stage cp.async pipeline + ldmatrix ================
// CTA 128x128, K-chunk 32. Swizzle: byte = row*128 + ((col16 ^ (row&7))<<4).
// grid: (N/128, ceil(M/128), Sr*nbatch). z: s=z%Sr, b=z/Sr.
__global__ void __launch_bounds__(256,2) wgemm(
    int M, int nchunks, int Sr,
    const uint32_t* __restrict__ A, int lda, long long sAb,
    const uint32_t* __restrict__ BT, int ldbt, long long sBTb,
    const uint32_t* __restrict__ A2, const uint32_t* __restrict__ BT2,
    float* __restrict__ dst1, int ld1, long long d1b, float* __restrict__ dst1b,
    float* __restrict__ dst2, int ld2, long long d2b,
    const float* __restrict__ bias, const float* __restrict__ bias2,
    int relu, int tf32out,
    float* __restrict__ part, int Mtot, int Nn)
{
    extern __shared__ float smf[];
    uint32_t sbase = (uint32_t)__cvta_generic_to_shared(smf);
    int tid = threadIdx.x;
    int lane = tid & 31, wid = tid >> 5;
    int wm = wid >> 2, wn = wid & 3;
    int m0 = blockIdx.y*128, n0 = blockIdx.x*128;
    int z = blockIdx.z;
    int s = z % Sr, b = z / Sr;
    const uint32_t* Ause;
    const uint32_t* BTuse;
    float* d1; float* d2;
    const float* biasu;
    if (A2) {
        Ause  = b ? A2  : A;
        BTuse = b ? BT2 : BT;
        d1 = b ? dst1b : dst1;
        d2 = dst2;
        biasu = (b && bias2) ? bias2 : bias;
    } else {
        Ause  = A + (size_t)b*sAb;
        BTuse = BT + (size_t)b*sBTb;
        d1 = dst1 ? dst1 + (size_t)b*d1b : nullptr;
        d2 = dst2 ? dst2 + (size_t)b*d2b : nullptr;
        biasu = bias;
    }
    int kbase = s*nchunks*32;

    int r0g = tid >> 3;
    int qf  = tid & 7;
    uint32_t dstoff[4];
    const uint32_t* aS[4]; uint32_t aSz[4];
    const uint32_t* bS[4];
    #pragma unroll
    for (int t = 0; t < 4; t++) {
        int r = r0g + t*32;
        dstoff[t] = (uint32_t)(r*128) + (uint32_t)((qf ^ (r & 7)) << 4);
        int rm = m0 + r;
        int rcl = rm < M ? rm : (M-1);
        aS[t]  = Ause + (size_t)rcl*lda + kbase + qf*4;
        aSz[t] = (rm < M) ? 16u : 0u;
        bS[t]  = BTuse + (size_t)(n0 + r)*ldbt + kbase + qf*4;
    }

    int lg = lane >> 3, l7 = lane & 7;
    int arow = wm*64 + ((lg & 1) << 3) + l7;
    int brow = wn*32 + ((lg >> 1) << 3) + l7;
    uint32_t acol[4], bcol[4];
    #pragma unroll
    for (int ks = 0; ks < 4; ks++) {
        acol[ks] = (uint32_t)(((((ks<<1) + (lg>>1)) ^ (arow & 7))) << 4);
        bcol[ks] = (uint32_t)(((((ks<<1) + (lg&1))  ^ (brow & 7))) << 4);
    }
    uint32_t aBase = sbase + (uint32_t)(arow*128);
    uint32_t bBase = sbase + 16384u + (uint32_t)(brow*128);

    float acc[4][4][4];
    #pragma unroll
    for (int i = 0; i < 4; i++)
        #pragma unroll
        for (int j = 0; j < 4; j++)
            #pragma unroll
            for (int k = 0; k < 4; k++) acc[i][j][k] = 0.f;

    auto issue = [&](int kc, int st) {
        uint32_t off = sbase + (uint32_t)(st*32768);
        int ko = kc*32;
        #pragma unroll
        for (int t = 0; t < 4; t++) {
            cpa16(off + dstoff[t], aS[t] + ko, aSz[t]);
            cpa16(off + 16384u + dstoff[t], bS[t] + ko, 16u);
        }
        CP_COMMIT();
    };
    auto compute = [&](int st) {
        uint32_t ab = aBase + (uint32_t)(st*32768);
        uint32_t bb = bBase + (uint32_t)(st*32768);
        #pragma unroll
        for (int ks = 0; ks < 4; ks++) {
            uint32_t bfr[4][2];
            #pragma unroll
            for (int ntp = 0; ntp < 2; ntp++)
                ldsm4(bb + (uint32_t)(ntp*2048) + bcol[ks],
                      bfr[2*ntp][0], bfr[2*ntp][1], bfr[2*ntp+1][0], bfr[2*ntp+1][1]);
            #pragma unroll
            for (int mt = 0; mt < 4; mt++) {
                uint32_t a0, a1, a2, a3;
                ldsm4(ab + (uint32_t)(mt*2048) + acol[ks], a0, a1, a2, a3);
                #pragma unroll
                for (int nt = 0; nt < 4; nt++)
                    mma_tf32(acc[mt][nt], a0, a1, a2, a3, bfr[nt][0], bfr[nt][1]);
            }
        }
    };

    issue(0, 0);
    if (nchunks > 1) issue(1, 1);
    int st = 0;
    for (int kc = 0; kc < nchunks; kc++) {
        if (kc + 1 < nchunks) CP_WAIT1(); else CP_WAIT0();
        __syncthreads();
        if (kc + 2 < nchunks) {
            int st2 = st + 2; if (st2 >= 3) st2 -= 3;
            issue(kc + 2, st2);
        }
        compute(st);
        st = (st == 2) ? 0 : st + 1;
    }

    int eg = lane >> 2, ec = lane & 3;
    #pragma unroll
    for (int mt = 0; mt < 4; mt++) {
        int r0 = m0 + wm*64 + mt*16 + eg;
        int r1 = r0 + 8;
        #pragma unroll
        for (int nt = 0; nt < 4; nt++) {
            int c0 = n0 + wn*32 + nt*8 + 2*ec;
            if (part) {
                float* p0 = part + ((size_t)z*Mtot + r0)*Nn + c0;
                float* p1 = part + ((size_t)z*Mtot + r1)*Nn + c0;
                if (r0 < M) { p0[0] = acc[mt][nt][0]; p0[1] = acc[mt][nt][1]; }
                if (r1 < M) { p1[0] = acc[mt][nt][2]; p1[1] = acc[mt][nt][3]; }
            } else {
                float b0 = biasu ? biasu[c0] : 0.f;
                float b1 = biasu ? biasu[c0+1] : 0.f;
                float v0 = acc[mt][nt][0] + b0, v1 = acc[mt][nt][1] + b1;
                float v2 = acc[mt][nt][2] + b0, v3 = acc[mt][nt][3] + b1;
                if (relu) { v0=fmaxf(v0,0.f); v1=fmaxf(v1,0.f); v2=fmaxf(v2,0.f); v3=fmaxf(v3,0.f); }
                if (tf32out) {
                    uint32_t u0 = f2tf32(v0), u1 = f2tf32(v1), u2 = f2tf32(v2), u3 = f2tf32(v3);
                    if (r0 < M) {
                        ((uint32_t*)d1)[(size_t)r0*ld1 + c0] = u0;
                        ((uint32_t*)d1)[(size_t)r0*ld1 + c0+1] = u1;
                        if (d2) { ((uint32_t*)d2)[(size_t)r0*ld2 + c0] = u0;
                                  ((uint32_t*)d2)[(size_t)r0*ld2 + c0+1] = u1; }
                    }
                    if (r1 < M) {
                        ((uint32_t*)d1)[(size_t)r1*ld1 + c0] = u2;
                        ((uint32_t*)d1)[(size_t)r1*ld1 + c0+1] = u3;
                        if (d2) { ((uint32_t*)d2)[(size_t)r1*ld2 + c0] = u2;
                                  ((uint32_t*)d2)[(size_t)r1*ld2 + c0+1] = u3; }
                    }
                } else {
                    if (r0 < M) {
                        d1[(size_t)r0*ld1 + c0] = v0; d1[(size_t)r0*ld1 + c0+1] = v1;
                        if (d2) { d2[(size_t)r0*ld2 + c0] = v0; d2[(size_t)r0*ld2 + c0+1] = v1; }
                    }
                    if (r1 < M) {
                        d1[(size_t)r1*ld1 + c0] = v2; d1[(size_t)r1*ld1 + c0+1] = v3;
                        if (d2) { d2[(size_t)r1*ld2 + c0] = v2; d2[(size_t)r1*ld2 + c0+1] = v3; }
                    }
                }
            }
        }
    }
}

// ===== bilinear: grid (12 m-tiles, 24 slots). slot = kb*2 + half; 64 chunks each. =====
__global__ void __launch_bounds__(256,2) wbil(const uint32_t* __restrict__ BT)
{
    extern __shared__ float smf[];
    uint32_t sbase = (uint32_t)__cvta_generic_to_shared(smf);
    float* ts_s = smf + 16384;           // [128][64]
    int tid = threadIdx.x;
    int lane = tid & 31, wid = tid >> 5;
    int wm = wid >> 2, wn = wid & 3;
    int m0 = blockIdx.x*128;
    int slot = blockIdx.y;
    int kb = slot >> 1, half = slot & 1;

    #pragma unroll
    for (int t = 0; t < 8; t++) {
        int idx = tid + t*256;
        int r = idx >> 4, qi = idx & 15;
        int rg = m0 + r;
        float4 v = make_float4(0.f,0.f,0.f,0.f);
        if (rg < NP)
            v = *(const float4*)(g_ts + (size_t)rg*DD + kb*64 + qi*4);
        *(float4*)(ts_s + r*64 + qi*4) = v;
    }
    __syncthreads();

    int r0g = tid >> 3;
    int qf  = tid & 7;
    uint32_t dstoff[4];
    const uint32_t* bS[4];
    int hrow[4]; int hvalid[4];
    #pragma unroll
    for (int t = 0; t < 4; t++) {
        int r = r0g + t*32;
        dstoff[t] = (uint32_t)(r*128) + (uint32_t)((qf ^ (r & 7)) << 4);
        bS[t] = BT + (size_t)r*KBIL + kb*4096 + half*2048 + qf*4;
        hrow[t] = m0 + r;
        hvalid[t] = (m0 + r) < NP;
    }
    int icol0 = kb*64 + half*32;

    int lg = lane >> 3, l7 = lane & 7;
    int arow = wm*64 + ((lg & 1) << 3) + l7;
    int brow = wn*32 + ((lg >> 1) << 3) + l7;
    uint32_t acol[4], bcol[4];
    #pragma unroll
    for (int ks = 0; ks < 4; ks++) {
        acol[ks] = (uint32_t)(((((ks<<1) + (lg>>1)) ^ (arow & 7))) << 4);
        bcol[ks] = (uint32_t)(((((ks<<1) + (lg&1))  ^ (brow & 7))) << 4);
    }
    uint32_t aBase = sbase + (uint32_t)(arow*128);
    uint32_t bBase = sbase + 16384u + (uint32_t)(brow*128);

    float acc[4][4][4];
    #pragma unroll
    for (int i = 0; i < 4; i++)
        #pragma unroll
        for (int j = 0; j < 4; j++)
            #pragma unroll
            for (int k = 0; k < 4; k++) acc[i][j][k] = 0.f;

    float hv[4];
    float4 av[4];
    auto issueB = [&](int kc, int buf) {
        uint32_t off = sbase + (uint32_t)(buf*32768) + 16384u;
        int ko = kc*32;
        #pragma unroll
        for (int t = 0; t < 4; t++)
            cpa16(off + dstoff[t], bS[t] + ko, 16u);
        CP_COMMIT();
    };
    auto gatherA = [&](int kc) {
        if ((kc & 1) == 0) {
            int icol = icol0 + (kc >> 1);
            #pragma unroll
            for (int t = 0; t < 4; t++)
                hv[t] = hvalid[t] ? g_hs[(size_t)hrow[t]*DD + icol] : 0.f;
        }
        int j0 = ((kc & 1) << 5) + qf*4;
        #pragma unroll
        for (int t = 0; t < 4; t++) {
            int r = r0g + t*32;
            float4 tv = *(const float4*)(ts_s + r*64 + j0);
            av[t] = make_float4(hv[t]*tv.x, hv[t]*tv.y, hv[t]*tv.z, hv[t]*tv.w);
        }
    };
    auto storeA = [&](int buf) {
        uint32_t off = sbase + (uint32_t)(buf*32768);
        #pragma unroll
        for (int t = 0; t < 4; t++)
            sts128(off + dstoff[t],
                   f2tf32(av[t].x), f2tf32(av[t].y), f2tf32(av[t].z), f2tf32(av[t].w));
    };
    auto compute = [&](int buf) {
        uint32_t ab = aBase + (uint32_t)(buf*32768);
        uint32_t bb = bBase + (uint32_t)(buf*32768);
        #pragma unroll
        for (int ks = 0; ks < 4; ks++) {
            uint32_t bfr[4][2];
            #pragma unroll
            for (int ntp = 0; ntp < 2; ntp++)
                ldsm4(bb + (uint32_t)(ntp*2048) + bcol[ks],
                      bfr[2*ntp][0], bfr[2*ntp][1], bfr[2*ntp+1][0], bfr[2*ntp+1][1]);
            #pragma unroll
            for (int mt = 0; mt < 4; mt++) {
                uint32_t a0, a1, a2, a3;
                ldsm4(ab + (uint32_t)(mt*2048) + acol[ks], a0, a1, a2, a3);
                #pragma unroll
                for (int nt = 0; nt < 4; nt++)
                    mma_tf32(acc[mt][nt], a0, a1, a2, a3, bfr[nt][0], bfr[nt][1]);
            }
        }
    };

    issueB(0, 0);
    gatherA(0);
    for (int kc = 0; kc < 64; kc++) {
        int buf = kc & 1;
        storeA(buf);
        CP_WAIT0();
        __syncthreads();
        if (kc + 1 < 64) { issueB(kc + 1, buf ^ 1); gatherA(kc + 1); }
        compute(buf);
    }

    int eg = lane >> 2, ec = lane & 3;
    #pragma unroll
    for (int mt = 0; mt < 4; mt++) {
        int r0 = m0 + wm*64 + mt*16 + eg;
        int r1 = r0 + 8;
        #pragma unroll
        for (int nt = 0; nt < 4; nt++) {
            int c0 = wn*32 + nt*8 + 2*ec;
            #pragma unroll
            for (int u = 0; u < 2; u++) {
                int col = c0 + u;
                if (col < LL) {
                    if (r0 < NP) g_part[((size_t)slot*NP + r0)*LL + col] = acc[mt][nt][u];
                    if (r1 < NP) g_part[((size_t)slot*NP + r1)*LL + col] = acc[mt][nt][2+u];
                }
            }
        }
    }
}

// ================= transpose -> tf32 =================
__global__ void ktrans(const float* __restrict__ in, int R, int C, int Cout,
                       uint32_t* __restrict__ out)
{
    __shared__ float t[32][33];
    int c0 = blockIdx.x*32, r0 = blockIdx.y*32;
    int tx = threadIdx.x, ty = threadIdx.y;
    #pragma unroll
    for (int j = 0; j < 32; j += 8) {
        int r = r0 + ty + j, c = c0 + tx;
        t[ty+j][tx] = (r < R && c < C) ? in[(size_t)r*C + c] : 0.f;
    }
    __syncthreads();
    #pragma unroll
    for (int j = 0; j < 32; j += 8) {
        int c = c0 + ty + j, r = r0 + tx;
        if (c < Cout && r < R) out[(size_t)c*R + r] = f2tf32(t[tx][ty+j]);
    }
}

__global__ void ktransB(const float* __restrict__ in, uint32_t* __restrict__ out)
{
    __shared__ float t[32][33];
    int d0 = blockIdx.x*32, c0 = blockIdx.y*32, n = blockIdx.z;
    int tx = threadIdx.x, ty = threadIdx.y;
    const float* inb = in + (size_t)n*CC*DD;
    uint32_t* outb = out + (size_t)n*DD*CC;
    #pragma unroll
    for (int j = 0; j < 32; j += 8)
        t[ty+j][tx] = inb[(size_t)(c0+ty+j)*DD + d0 + tx];
    __syncthreads();
    #pragma unroll
    for (int j = 0; j < 32; j += 8)
        outb[(size_t)(d0+ty+j)*CC + c0 + tx] = f2tf32(t[tx][ty+j]);
}

// ---------------- K1: gather ----------------
__global__ void k_gather(const float* __restrict__ seq, const float* __restrict__ att,
                         const int* __restrict__ ms)
{
    int ne = blockIdx.x;
    int n  = ne / EE;
    int tid = threadIdx.x;
    for (int m = 0; m < MMENT; m++) {
        int pos = ms[ne*MMENT + m] + 1;
        const float* srow = seq + ((size_t)n*CC + pos)*DD;
        float* erow = g_eemb + ((size_t)ne*MMENT + m)*DD;
        for (int d = tid; d < DD; d += blockDim.x) erow[d] = srow[d];
        float* arow = g_eatt + ((size_t)ne*MMENT + m)*CC;
        for (int c = tid; c < CC; c += blockDim.x) {
            float s = 0.f;
            #pragma unroll
            for (int h = 0; h < HH; h++)
                s += att[(((size_t)n*HH + h)*CC + pos)*CC + c];
            arow[c] = s * (1.0f/HH);
        }
    }
    __syncthreads();
    for (int d = tid; d < DD; d += blockDim.x) {
        float x0 = g_eemb[((size_t)ne*MMENT+0)*DD+d];
        float x1 = g_eemb[((size_t)ne*MMENT+1)*DD+d];
        float x2 = g_eemb[((size_t)ne*MMENT+2)*DD+d];
        float x3 = g_eemb[((size_t)ne*MMENT+3)*DD+d];
        float mx = fmaxf(fmaxf(x0,x1), fmaxf(x2,x3));
        float s = expf(x0-mx)+expf(x1-mx)+expf(x2-mx)+expf(x3-mx);
        g_glob[(size_t)ne*DD + d] = mx + logf(s);
    }
}

// ---------------- K3: edge ----------------
__global__ void k_edge(const float* __restrict__ bm)
{
    int idx = blockIdx.x*blockDim.x + threadIdx.x;
    const int total = NN*EE*EE*DD;
    if (idx >= total) return;
    int d = idx % DD;
    int v = (idx / DD) % EE;
    int u = (idx / (DD*EE)) % EE;
    int n = idx / (DD*EE*EE);
    float val = g_A[((size_t)n*EE+u)*DD+d] + g_B[((size_t)n*EE+v)*DD+d] + bm[d];
    g_edge[idx] = fmaxf(val, 0.f);
}

// ---------------- K4: pair attention ----------------
__global__ void k_pair(const int* __restrict__ hts, const int* __restrict__ ms)
{
    int r = blockIdx.x;
    int n = r / PP;
    int h = hts[r*2 + 0];
    int t = hts[r*2 + 1];
    __shared__ int   s_ph[MMENT], s_pt[MMENT];
    __shared__ float s_phatt[MMENT], s_ptatt[MMENT];
    __shared__ float s_red[256];
    int tid = threadIdx.x;
    if (tid < MMENT) {
        s_ph[tid] = ms[((size_t)n*EE+h)*MMENT + tid] + 1;
        s_pt[tid] = ms[((size_t)n*EE+t)*MMENT + tid] + 1;
    }
    __syncthreads();
    if (tid < 2*MMENT) {
        int m2 = tid & (MMENT-1);
        float s = 0.f;
        if (tid < MMENT) {
            for (int m1 = 0; m1 < MMENT; m1++)
                s += g_eatt[((size_t)(n*EE+h)*MMENT+m1)*CC + s_pt[m2]];
            s_phatt[m2] = s * (1.f/MMENT);
        } else {
            for (int m1 = 0; m1 < MMENT; m1++)
                s += g_eatt[((size_t)(n*EE+t)*MMENT+m1)*CC + s_ph[m2]];
            s_ptatt[m2] = s * (1.f/MMENT);
        }
    }
    __syncthreads();
    if (tid == 0) {
        float sh = 1e-5f, st = 1e-5f;
        for (int m = 0; m < MMENT; m++) { sh += s_phatt[m]; st += s_ptatt[m]; }
        float ih = 1.f/sh, it = 1.f/st;
        for (int m = 0; m < MMENT; m++) { s_phatt[m] *= ih; s_ptatt[m] *= it; }
    }
    __syncthreads();
    for (int d = tid; d < DD; d += blockDim.x) {
        float nh = 0.f, nt = 0.f;
        #pragma unroll
        for (int m = 0; m < MMENT; m++) {
            nh += s_ptatt[m]*g_eemb[((size_t)(n*EE+h)*MMENT+m)*DD + d];
            nt += s_phatt[m]*g_eemb[((size_t)(n*EE+t)*MMENT+m)*DD + d];
        }
        uint32_t nh32 = f2tf32(nh), nt32 = f2tf32(nt);
        g_hcat32[(size_t)r*DIM3 + d] = nh32;
        g_tcat32[(size_t)r*DIM3 + d] = nt32;
        g_q32[(size_t)r*DIM2 + d]      = nh32;
        g_q32[(size_t)r*DIM2 + DD + d] = nt32;
    }
    float local = 0.f;
    for (int c = tid; c < CC; c += blockDim.x) {
        float na = 0.f, ta = 0.f;
        #pragma unroll
        for (int m = 0; m < MMENT; m++) {
            na += s_ptatt[m]*g_eatt[((size_t)(n*EE+h)*MMENT+m)*CC + c];
            ta += s_phatt[m]*g_eatt[((size_t)(n*EE+t)*MMENT+m)*CC + c];
        }
        float v = na*ta;
        g_pa[(size_t)r*CC + c] = v;
        local += v;
    }
    s_red[tid] = local;
    __syncthreads();
    for (int off = 128; off > 0; off >>= 1) {
        if (tid < off) s_red[tid] += s_red[tid+off];
        __syncthreads();
    }
    float inv = 1.f/(s_red[0] + 1e-5f);
    for (int c = tid; c < CC; c += blockDim.x)
        g_pa32[(size_t)r*CC + c] = f2tf32(g_pa[(size_t)r*CC + c]*inv);
}

// ---------------- fp32 SGEMM (Wm1+Wm2 merged) ----------------
__global__ void __launch_bounds__(256) sgemm(
    int M, int Nn, int Kc, int S,
    const float* __restrict__ A, int lda,
    const float* __restrict__ B, const float* __restrict__ B2, int ldb,
    float* __restrict__ part)
{
    int z = blockIdx.z;
    int s = z % S, b = z / S;
    const float* Ab = A + (size_t)s*Kc;
    const float* Bb = ((b && B2) ? B2 : B) + (size_t)s*Kc*ldb;
    int m0 = blockIdx.y*128, n0 = blockIdx.x*128;
    __shared__ float As[8][128];
    __shared__ float Bs[8][128];
    int tid = threadIdx.x;
    int arow = tid >> 1, ak = (tid & 1)*4;
    int bk = tid >> 5,  bn = (tid & 31)*4;
    int tx = tid & 15,  ty = tid >> 4;
    float acc[8][8];
    #pragma unroll
    for (int i = 0; i < 8; i++)
        #pragma unroll
        for (int j = 0; j < 8; j++) acc[i][j] = 0.f;
    for (int k0 = 0; k0 < Kc; k0 += 8) {
        float4 av = make_float4(0.f,0.f,0.f,0.f);
        if (m0 + arow < M)
            av = *(const float4*)(Ab + (size_t)(m0+arow)*lda + k0 + ak);
        float4 bvv = *(const float4*)(Bb + (size_t)(k0+bk)*ldb + n0 + bn);
        __syncthreads();
        As[ak+0][arow] = av.x; As[ak+1][arow] = av.y;
        As[ak+2][arow] = av.z; As[ak+3][arow] = av.w;
        *(float4*)&Bs[bk][bn] = bvv;
        __syncthreads();
        #pragma unroll
        for (int kk = 0; kk < 8; kk++) {
            float a[8], bb[8];
            *(float4*)(a)    = *(const float4*)&As[kk][ty*8];
            *(float4*)(a+4)  = *(const float4*)&As[kk][ty*8+4];
            *(float4*)(bb)   = *(const float4*)&Bs[kk][tx*8];
            *(float4*)(bb+4) = *(const float4*)&Bs[kk][tx*8+4];
            #pragma unroll
            for (int i = 0; i < 8; i++)
                #pragma unroll
                for (int j = 0; j < 8; j++)
                    acc[i][j] += a[i]*bb[j];
        }
    }
    float* pbase = part + ((size_t)z*M)*Nn;
    #pragma unroll
    for (int i = 0; i < 8; i++) {
        int r = m0 + ty*8 + i;
        if (r < M) {
            float* prow = pbase + (size_t)r*Nn + n0 + tx*8;
            *(float4*)(prow)   = make_float4(acc[i][0],acc[i][1],acc[i][2],acc[i][3]);
            *(float4*)(prow+4) = make_float4(acc[i][4],acc[i][5],acc[i][6],acc[i][7]);
        }
    }
}

__global__ void reduce_ep(const float* __restrict__ part, int S, int Mtot, int Nn,
                          const float* __restrict__ bias, int dorelu, int tf32out,
                          float* __restrict__ dst1, int ld1,
                          float* __restrict__ dst2, int ld2)
{
    int idx = blockIdx.x*blockDim.x + threadIdx.x;
    if (idx >= Mtot*Nn) return;
    int r = idx / Nn, c = idx % Nn;
    float v = 0.f;
    for (int s = 0; s < S; s++)
        v += part[((size_t)s*Mtot + r)*Nn + c];
    if (bias) v += bias[c];
    if (dorelu) v = fmaxf(v, 0.f);
    if (tf32out) {
        uint32_t u = f2tf32(v);
        ((uint32_t*)dst1)[(size_t)r*ld1 + c] = u;
        if (dst2) ((uint32_t*)dst2)[(size_t)r*ld2 + c] = u;
    } else {
        dst1[(size_t)r*ld1 + c] = v;
        if (dst2) dst2[(size_t)r*ld2 + c] = v;
    }
}

// ---------------- grouped score: block (e, kk, n) ----------------
// spart[kk][p][v] = q_kk[p] . edge_slice[v]
__global__ void __launch_bounds__(256) k_score(const float* __restrict__ qW)
{
    extern __shared__ float sm[];    // [20][768]
    int e = blockIdx.x, kk = blockIdx.y, n = blockIdx.z;
    int tid = threadIdx.x;
    bool strided = (kk == 1) || (kk == 3);
    bool grouph  = (kk == 0) || (kk == 3);
    for (int idx = tid; idx < EE*DD; idx += 256) {
        int v = idx / DD, d = idx % DD;
        size_t off = strided ? (((size_t)(n*EE + v)*EE + e))*DD + d
                             : (((size_t)(n*EE + e)*EE + v))*DD + d;
        sm[idx] = g_edge[off];
    }
    __syncthreads();
    int wid = tid >> 5, lane = tid & 31;
    for (int jj = wid; jj < EE-1; jj += 8) {
        int p = group_pair(n, e, jj, grouph);
        const float* qrow = qW + (size_t)p*DIM4 + kk*DD;
        float q[24];
        #pragma unroll
        for (int u = 0; u < 24; u++) q[u] = qrow[lane + 32*u];
        for (int v = 0; v < EE; v++) {
            const float* smv = sm + v*DD;
            float acc = 0.f;
            #pragma unroll
            for (int u = 0; u < 24; u++) acc += q[u]*smv[lane + 32*u];
            #pragma unroll
            for (int o = 16; o; o >>= 1) acc += __shfl_down_sync(0xffffffffu, acc, o);
            if (lane == 0) g_spart[((size_t)kk*NP + p)*EE + v] = acc;
        }
    }
}

// ---------------- softmax over v (masked) ----------------
__global__ void k_softmax(const int* __restrict__ hts, const float* __restrict__ battp)
{
    int p = blockIdx.x;
    int lane = threadIdx.x;
    int h = hts[p*2], t = hts[p*2+1];
    float s = -1e38f;
    if (lane < EE) {
        s = g_spart[((size_t)0*NP+p)*EE+lane] + g_spart[((size_t)1*NP+p)*EE+lane]
          + g_spart[((size_t)2*NP+p)*EE+lane] + g_spart[((size_t)3*NP+p)*EE+lane]
          + battp[0];
        if (lane == h || lane == t) s = NEGV;
    }
    float mx = s;
    #pragma unroll
    for (int o = 16; o; o >>= 1) mx = fmaxf(mx, __shfl_xor_sync(0xffffffffu, mx, o));
    float ex = (lane < EE) ? expf(s - mx) : 0.f;
    float sum = ex;
    #pragma unroll
    for (int o = 16; o; o >>= 1) sum += __shfl_xor_sync(0xffffffffu, sum, o);
    if (lane < EE) g_aw[(size_t)p*EE + lane] = ex/sum;
}

// ---------------- grouped path: praw[p, kk*768+d] = sum_v aw[p,v]*slice[v,d] ----------------
__global__ void __launch_bounds__(256) k_pathg()
{
    extern __shared__ float sm[];    // [20][768] + aw [19][20]
    float* aws = sm + EE*DD;
    int e = blockIdx.x, kk = blockIdx.y, n = blockIdx.z;
    int tid = threadIdx.x;
    bool strided = (kk == 1) || (kk == 3);
    bool grouph  = (kk == 0) || (kk == 3);
    for (int idx = tid; idx < EE*DD; idx += 256) {
        int v = idx / DD, d = idx % DD;
        size_t off = strided ? (((size_t)(n*EE + v)*EE + e))*DD + d
                             : (((size_t)(n*EE + e)*EE + v))*DD + d;
        sm[idx] = g_edge[off];
    }
    for (int idx = tid; idx < 19*EE; idx += 256) {
        int jj = idx / EE, v = idx % EE;
        int p = group_pair(n, e, jj, grouph);
        aws[idx] = g_aw[(size_t)p*EE + v];
    }
    __syncthreads();
    for (int idx = tid; idx < 19*DD; idx += 256) {
        int jj = idx / DD, d = idx % DD;
        float acc = 0.f;
        #pragma unroll
        for (int v = 0; v < EE; v++)
            acc += aws[jj*EE + v]*sm[v*DD + d];
        int p = group_pair(n, e, jj, grouph);
        g_praw32[(size_t)p*DIM4 + kk*DD + d] = f2tf32(acc);
    }
}

__global__ void k_bilred(const float* __restrict__ bbil, float* __restrict__ out)
{
    int idx = blockIdx.x*blockDim.x + threadIdx.x;
    if (idx >= NP*LL) return;
    int r = idx / LL, l = idx % LL;
    float v = bbil[l];
    #pragma unroll
    for (int k = 0; k < 24; k++)
        v += g_part[((size_t)k*NP + r)*LL + l];
    out[idx] = v;
}

// ---------------- launcher ----------------
static void* symaddr(const void* sym)
{
    void* p = nullptr;
    cudaGetSymbolAddress(&p, sym);
    return p;
}

extern "C" void kernel_launch(void* const* d_in, const int* in_sizes, int n_in,
                              void* d_out, int out_size)
{
    const float* seq   = (const float*)d_in[0];
    const float* att   = (const float*)d_in[1];
    const int*   ms    = (const int*)  d_in[2];
    const int*   hts   = (const int*)  d_in[3];
    const float* Wm1   = (const float*)d_in[4];
    const float* Wm2   = (const float*)d_in[5];
    const float* bm    = (const float*)d_in[6];
    const float* Watt  = (const float*)d_in[7];
    const float* batt  = (const float*)d_in[8];
    const float* Wpath = (const float*)d_in[9];
    const float* bpath = (const float*)d_in[10];
    const float* Whead = (const float*)d_in[11];
    const float* bhead = (const float*)d_in[12];
    const float* Wtail = (const float*)d_in[13];
    const float* btail = (const float*)d_in[14];
    const float* Wbil  = (const float*)d_in[15];
    const float* bbil  = (const float*)d_in[16];
    float* out = (float*)d_out;

    float*    glob   = (float*)symaddr(g_glob);
    float*    gA     = (float*)symaddr(g_A);
    float*    gB     = (float*)symaddr(g_B);
    float*    qW     = (float*)symaddr(g_qW);
    float*    hs     = (float*)symaddr(g_hs);
    float*    ts     = (float*)symaddr(g_ts);
    float*    part   = (float*)symaddr(g_part);
    uint32_t* pa32   = (uint32_t*)symaddr(g_pa32);
    uint32_t* seqT32 = (uint32_t*)symaddr(g_seqT32);
    uint32_t* q32    = (uint32_t*)symaddr(g_q32);
    uint32_t* hcat32 = (uint32_t*)symaddr(g_hcat32);
    uint32_t* tcat32 = (uint32_t*)symaddr(g_tcat32);
    uint32_t* praw32 = (uint32_t*)symaddr(g_praw32);
    uint32_t* wTatt  = (uint32_t*)symaddr(g_wT_att32);
    uint32_t* wTpath = (uint32_t*)symaddr(g_wT_path32);
    uint32_t* wThead = (uint32_t*)symaddr(g_wT_head32);
    uint32_t* wTtail = (uint32_t*)symaddr(g_wT_tail32);
    uint32_t* wTbil  = (uint32_t*)symaddr(g_wT_bil32);

    const int SMEM_WG = 98304;           // 3 stages x 32KB
    const int SMEM_WB = 98304;
    const int SMEM_SC = EE*DD*4;         // 61440
    const int SMEM_PG = EE*DD*4 + 19*EE*4;
    cudaFuncSetAttribute(wgemm,  cudaFuncAttributeMaxDynamicSharedMemorySize, SMEM_WG);
    cudaFuncSetAttribute(wbil,   cudaFuncAttributeMaxDynamicSharedMemorySize, SMEM_WB);
    cudaFuncSetAttribute(k_score, cudaFuncAttributeMaxDynamicSharedMemorySize, SMEM_SC);
    cudaFuncSetAttribute(k_pathg, cudaFuncAttributeMaxDynamicSharedMemorySize, SMEM_PG);

    // --- ordered so launch index 3 (ncu capture slot) is the qW wgemm ---
    k_gather<<<NN*EE, 256>>>(seq, att, ms);                                        // 0
    k_pair<<<NP, 256>>>(hts, ms);                                                  // 1
    ktrans<<<dim3(DIM4/32, DIM2/32), dim3(32,8)>>>(Watt, DIM2, DIM4, DIM4, wTatt); // 2
    // 3: qW = q @ Watt (tf32 mma, 3-stage pipeline) <-- ncu profiles this
    wgemm<<<dim3(24,12,1), 256, SMEM_WG>>>(NP, 48, 1,
        q32, DIM2, 0, wTatt, DIM2, 0, nullptr, nullptr,
        qW, DIM4, 0, nullptr, nullptr, 0, 0,
        nullptr, nullptr, 0, 0, nullptr, 0, 0);

    // Wm1+Wm2 merged (fp32, split-K 12 each)
    sgemm<<<dim3(6,1,24), 256>>>(NN*EE, DD, 64, 12, glob, DD, Wm1, Wm2, DD, part);
    reduce_ep<<<(NN*EE*DD+255)/256, 256>>>(part, 12, NN*EE, DD, nullptr, 0, 0,
                                           gA, DD, nullptr, 0);
    reduce_ep<<<(NN*EE*DD+255)/256, 256>>>(part + (size_t)12*NN*EE*DD, 12, NN*EE, DD,
                                           nullptr, 0, 0, gB, DD, nullptr, 0);
    k_edge<<<(NN*EE*EE*DD+255)/256, 256>>>(bm);

    // rs = pa @ seq (tf32 mma, per-doc batch, direct dual tf32 epilogue)
    ktransB<<<dim3(DD/32, CC/32, NN), dim3(32,8)>>>(seq, seqT32);
    wgemm<<<dim3(6,3,NN), 256, SMEM_WG>>>(PP, 16, 1,
        pa32, CC, (long long)PP*CC, seqT32, CC, (long long)DD*CC, nullptr, nullptr,
        (float*)(hcat32 + DD), DIM3, (long long)PP*DIM3, nullptr,
        (float*)(tcat32 + DD), DIM3, (long long)PP*DIM3,
        nullptr, nullptr, 0, 1, nullptr, 0, 0);

    // grouped score -> softmax -> grouped path (replaces k_scorepath)
    k_score<<<dim3(EE,4,NN), 256, SMEM_SC>>>(qW);
    k_softmax<<<NP, 32>>>(hts, batt);
    k_pathg<<<dim3(EE,4,NN), 256, SMEM_PG>>>();

    // path = relu(pathraw @ Wpath + bpath) -> tf32 into hcat32/tcat32 [2D,3D)
    ktrans<<<dim3(DD/32, DIM4/32), dim3(32,8)>>>(Wpath, DIM4, DD, DD, wTpath);
    wgemm<<<dim3(6,12,2), 256, SMEM_WG>>>(NP, 48, 2,
        praw32, DIM4, 0, wTpath, DIM4, 0, nullptr, nullptr,
        nullptr, 0, 0, nullptr, nullptr, 0, 0,
        nullptr, nullptr, 0, 0, part, NP, DD);
    reduce_ep<<<(NP*DD+255)/256, 256>>>(part, 2, NP, DD, bpath, 1, 1,
                                        (float*)(hcat32 + 2*DD), DIM3,
                                        (float*)(tcat32 + 2*DD), DIM3);

    // hs / ts projections — merged, Sr=1, direct epilogue
    ktrans<<<dim3(DD/32, DIM3/32), dim3(32,8)>>>(Whead, DIM3, DD, DD, wThead);
    ktrans<<<dim3(DD/32, DIM3/32), dim3(32,8)>>>(Wtail, DIM3, DD, DD, wTtail);
    wgemm<<<dim3(6,12,2), 256, SMEM_WG>>>(NP, 72, 1,
        hcat32, DIM3, 0, wThead, DIM3, 0, tcat32, wTtail,
        hs, DD, 0, ts, nullptr, 0, 0,
        bhead, btail, 1, 0, nullptr, 0, 0);

    // bilinear head: grid (12, 24), partial slots 0..23
    ktrans<<<dim3(4, KBIL/32), dim3(32,8)>>>(Wbil, KBIL, LL, 128, wTbil);
    wbil<<<dim3(12,24), 256, SMEM_WB>>>(wTbil);
    k_bilred<<<(NP*LL+255)/256, 256>>>(bbil, out);
}

// round 15
// speedup vs baseline: 1.0024x; 1.0024x over previous
#include <cuda_runtime.h>
#include <cstdint>
#include <math.h>

#define NN 4
#define CC 512
#define DD 768
#define HH 12
#define EE 20
#define MMENT 4
#define PP 380
#define NP 1520
#define LL 97
#define DIM2 1536
#define DIM3 2304
#define DIM4 3072
#define KBIL 49152
#define NEGV (-1e30f)

// ---------------- static device scratch ----------------
__device__ float g_eemb[NN*EE*MMENT*DD];
__device__ float g_eatt[NN*EE*MMENT*CC];
__device__ float g_glob[NN*EE*DD];
__device__ float g_A[NN*EE*DD];
__device__ float g_B[NN*EE*DD];
__device__ float g_edge[NN*EE*EE*DD];
__device__ float g_pa[NP*CC];
__device__ float g_qW[NP*DIM4];
__device__ float g_hs[NP*DD];
__device__ float g_ts[NP*DD];
__device__ float g_part[4*NP*DD];
__device__ float g_partm[24*NN*EE*DD];
__device__ float g_spart[4*NP*EE];
__device__ float g_aw[NP*EE];
// tf32 (u32 bit pattern) GEMM operands
__device__ uint32_t g_pa32[NP*CC];
__device__ uint32_t g_seqT32[NN*DD*CC];
__device__ uint32_t g_q32[NP*DIM2];
__device__ uint32_t g_hcat32[NP*DIM3];
__device__ uint32_t g_tcat32[NP*DIM3];
__device__ uint32_t g_praw32[NP*DIM4];
__device__ uint32_t g_wT_att32[DIM4*DIM2];
__device__ uint32_t g_wT_path32[DD*DIM4];
__device__ uint32_t g_wT_head32[DD*DIM3];
__device__ uint32_t g_wT_tail32[DD*DIM3];
__device__ uint32_t g_wT_bil32[128*KBIL];   // rows 97..127 zero

// ---------------- helpers ----------------
__device__ __forceinline__ uint32_t f2tf32(float f) {
    uint32_t r;
    asm("cvt.rna.tf32.f32 %0, %1;" : "=r"(r) : "f"(f));
    return r;
}
__device__ __forceinline__ void mma_tf32(float* d, uint32_t a0, uint32_t a1,
                                         uint32_t a2, uint32_t a3,
                                         uint32_t b0, uint32_t b1)
{
    asm volatile(
        "mma.sync.aligned.m16n8k8.row.col.f32.tf32.tf32.f32 "
        "{%0,%1,%2,%3}, {%4,%5,%6,%7}, {%8,%9}, {%0,%1,%2,%3};"
        : "+f"(d[0]), "+f"(d[1]), "+f"(d[2]), "+f"(d[3])
        : "r"(a0), "r"(a1), "r"(a2), "r"(a3), "r"(b0), "r"(b1));
}
__device__ __forceinline__ void ldsm4(uint32_t addr, uint32_t& a, uint32_t& b,
                                      uint32_t& c, uint32_t& d)
{
    asm volatile("ldmatrix.sync.aligned.m8n8.x4.shared.b16 {%0,%1,%2,%3}, [%4];"
                 : "=r"(a), "=r"(b), "=r"(c), "=r"(d) : "r"(addr));
}
__device__ __forceinline__ void sts128(uint32_t addr, uint32_t x, uint32_t y,
                                       uint32_t z, uint32_t w)
{
    asm volatile("st.shared.v4.b32 [%0], {%1,%2,%3,%4};"
                 :: "r"(addr), "r"(x), "r"(y), "r"(z), "r"(w) : "memory");
}
__device__ __forceinline__ void cpa16(uint32_t dst, const void* src, uint32_t sz)
{
    asm volatile("cp.async.cg.shared.global [%0], [%1], 16, %2;"
                 :: "r"(dst), "l"(src), "r"(sz) : "memory");
}
#define CP_COMMIT() asm volatile("cp.async.commit_group;" ::: "memory")
#define CP_WAIT0()  asm volatile("cp.async.wait_group 0;" ::: "memory")
#define CP_WAIT1()  asm volatile("cp.async.wait_group 1;" ::: "memory")

// pair-index helper
__device__ __forceinline__ int group_pair(int n, int e, int jj, bool grouph)
{
    if (grouph) return n*PP + e*19 + jj;
    int i = jj + (jj >= e);
    return n*PP + i*19 + (e < i ? e : e - 1);
}

// ================ tf32 warp-mma GEMM: 3-stage cp.async pipeline + ldmatrix ================
__global__ void __launch_bounds__(256,2) wgemm(
    int M, int nchunks, int Sr,
    const uint32_t* __restrict__ A, int lda, long long sAb,
    const uint32_t* __restrict__ BT, int ldbt, long long sBTb,
    const uint32_t* __restrict__ A2, const uint32_t* __restrict__ BT2,
    float* __restrict__ dst1, int ld1, long long d1b, float* __restrict__ dst1b,
    float* __restrict__ dst2, int ld2, long long d2b,
    const float* __restrict__ bias, const float* __restrict__ bias2,
    int relu, int tf32out,
    float* __restrict__ part, int Mtot, int Nn)
{
    extern __shared__ float smf[];
    uint32_t sbase = (uint32_t)__cvta_generic_to_shared(smf);
    int tid = threadIdx.x;
    int lane = tid & 31, wid = tid >> 5;
    int wm = wid >> 2, wn = wid & 3;
    int m0 = blockIdx.y*128, n0 = blockIdx.x*128;
    int z = blockIdx.z;
    int s = z % Sr, b = z / Sr;
    const uint32_t* Ause;
    const uint32_t* BTuse;
    float* d1; float* d2;
    const float* biasu;
    if (A2) {
        Ause  = b ? A2  : A;
        BTuse = b ? BT2 : BT;
        d1 = b ? dst1b : dst1;
        d2 = dst2;
        biasu = (b && bias2) ? bias2 : bias;
    } else {
        Ause  = A + (size_t)b*sAb;
        BTuse = BT + (size_t)b*sBTb;
        d1 = dst1 ? dst1 + (size_t)b*d1b : nullptr;
        d2 = dst2 ? dst2 + (size_t)b*d2b : nullptr;
        biasu = bias;
    }
    int kbase = s*nchunks*32;

    int r0g = tid >> 3;
    int qf  = tid & 7;
    uint32_t dstoff[4];
    const uint32_t* aS[4]; uint32_t aSz[4];
    const uint32_t* bS[4];
    #pragma unroll
    for (int t = 0; t < 4; t++) {
        int r = r0g + t*32;
        dstoff[t] = (uint32_t)(r*128) + (uint32_t)((qf ^ (r & 7)) << 4);
        int rm = m0 + r;
        int rcl = rm < M ? rm : (M-1);
        aS[t]  = Ause + (size_t)rcl*lda + kbase + qf*4;
        aSz[t] = (rm < M) ? 16u : 0u;
        bS[t]  = BTuse + (size_t)(n0 + r)*ldbt + kbase + qf*4;
    }

    int lg = lane >> 3, l7 = lane & 7;
    int arow = wm*64 + ((lg & 1) << 3) + l7;
    int brow = wn*32 + ((lg >> 1) << 3) + l7;
    uint32_t acol[4], bcol[4];
    #pragma unroll
    for (int ks = 0; ks < 4; ks++) {
        acol[ks] = (uint32_t)(((((ks<<1) + (lg>>1)) ^ (arow & 7))) << 4);
        bcol[ks] = (uint32_t)(((((ks<<1) + (lg&1))  ^ (brow & 7))) << 4);
    }
    uint32_t aBase = sbase + (uint32_t)(arow*128);
    uint32_t bBase = sbase + 16384u + (uint32_t)(brow*128);

    float acc[4][4][4];
    #pragma unroll
    for (int i = 0; i < 4; i++)
        #pragma unroll
        for (int j = 0; j < 4; j++)
            #pragma unroll
            for (int k = 0; k < 4; k++) acc[i][j][k] = 0.f;

    auto issue = [&](int kc, int st) {
        uint32_t off = sbase + (uint32_t)(st*32768);
        int ko = kc*32;
        #pragma unroll
        for (int t = 0; t < 4; t++) {
            cpa16(off + dstoff[t], aS[t] + ko, aSz[t]);
            cpa16(off + 16384u + dstoff[t], bS[t] + ko, 16u);
        }
        CP_COMMIT();
    };
    auto compute = [&](int st) {
        uint32_t ab = aBase + (uint32_t)(st*32768);
        uint32_t bb = bBase + (uint32_t)(st*32768);
        #pragma unroll
        for (int ks = 0; ks < 4; ks++) {
            uint32_t bfr[4][2];
            #pragma unroll
            for (int ntp = 0; ntp < 2; ntp++)
                ldsm4(bb + (uint32_t)(ntp*2048) + bcol[ks],
                      bfr[2*ntp][0], bfr[2*ntp][1], bfr[2*ntp+1][0], bfr[2*ntp+1][1]);
            #pragma unroll
            for (int mt = 0; mt < 4; mt++) {
                uint32_t a0, a1, a2, a3;
                ldsm4(ab + (uint32_t)(mt*2048) + acol[ks], a0, a1, a2, a3);
                #pragma unroll
                for (int nt = 0; nt < 4; nt++)
                    mma_tf32(acc[mt][nt], a0, a1, a2, a3, bfr[nt][0], bfr[nt][1]);
            }
        }
    };

    issue(0, 0);
    if (nchunks > 1) issue(1, 1);
    int st = 0;
    for (int kc = 0; kc < nchunks; kc++) {
        if (kc + 1 < nchunks) CP_WAIT1(); else CP_WAIT0();
        __syncthreads();
        if (kc + 2 < nchunks) {
            int st2 = st + 2; if (st2 >= 3) st2 -= 3;
            issue(kc + 2, st2);
        }
        compute(st);
        st = (st == 2) ? 0 : st + 1;
    }

    int eg = lane >> 2, ec = lane & 3;
    #pragma unroll
    for (int mt = 0; mt < 4; mt++) {
        int r0 = m0 + wm*64 + mt*16 + eg;
        int r1 = r0 + 8;
        #pragma unroll
        for (int nt = 0; nt < 4; nt++) {
            int c0 = n0 + wn*32 + nt*8 + 2*ec;
            if (part) {
                float* p0 = part + ((size_t)z*Mtot + r0)*Nn + c0;
                float* p1 = part + ((size_t)z*Mtot + r1)*Nn + c0;
                if (r0 < M) { p0[0] = acc[mt][nt][0]; p0[1] = acc[mt][nt][1]; }
                if (r1 < M) { p1[0] = acc[mt][nt][2]; p1[1] = acc[mt][nt][3]; }
            } else {
                float b0 = biasu ? biasu[c0] : 0.f;
                float b1 = biasu ? biasu[c0+1] : 0.f;
                float v0 = acc[mt][nt][0] + b0, v1 = acc[mt][nt][1] + b1;
                float v2 = acc[mt][nt][2] + b0, v3 = acc[mt][nt][3] + b1;
                if (relu) { v0=fmaxf(v0,0.f); v1=fmaxf(v1,0.f); v2=fmaxf(v2,0.f); v3=fmaxf(v3,0.f); }
                if (tf32out) {
                    uint32_t u0 = f2tf32(v0), u1 = f2tf32(v1), u2 = f2tf32(v2), u3 = f2tf32(v3);
                    if (r0 < M) {
                        ((uint32_t*)d1)[(size_t)r0*ld1 + c0] = u0;
                        ((uint32_t*)d1)[(size_t)r0*ld1 + c0+1] = u1;
                        if (d2) { ((uint32_t*)d2)[(size_t)r0*ld2 + c0] = u0;
                                  ((uint32_t*)d2)[(size_t)r0*ld2 + c0+1] = u1; }
                    }
                    if (r1 < M) {
                        ((uint32_t*)d1)[(size_t)r1*ld1 + c0] = u2;
                        ((uint32_t*)d1)[(size_t)r1*ld1 + c0+1] = u3;
                        if (d2) { ((uint32_t*)d2)[(size_t)r1*ld2 + c0] = u2;
                                  ((uint32_t*)d2)[(size_t)r1*ld2 + c0+1] = u3; }
                    }
                } else {
                    if (r0 < M) {
                        d1[(size_t)r0*ld1 + c0] = v0; d1[(size_t)r0*ld1 + c0+1] = v1;
                        if (d2) { d2[(size_t)r0*ld2 + c0] = v0; d2[(size_t)r0*ld2 + c0+1] = v1; }
                    }
                    if (r1 < M) {
                        d1[(size_t)r1*ld1 + c0] = v2; d1[(size_t)r1*ld1 + c0+1] = v3;
                        if (d2) { d2[(size_t)r1*ld2 + c0] = v2; d2[(size_t)r1*ld2 + c0+1] = v3; }
                    }
                }
            }
        }
    }
}

// ===== bilinear: grid (12 m-tiles, 24 slots). slot = kb*2 + half; 64 chunks each. =====
__global__ void __launch_bounds__(256,2) wbil(const uint32_t* __restrict__ BT)
{
    extern __shared__ float smf[];
    uint32_t sbase = (uint32_t)__cvta_generic_to_shared(smf);
    float* ts_s = smf + 16384;           // [128][64]
    int tid = threadIdx.x;
    int lane = tid & 31, wid = tid >> 5;
    int wm = wid >> 2, wn = wid & 3;
    int m0 = blockIdx.x*128;
    int slot = blockIdx.y;
    int kb = slot >> 1, half = slot & 1;

    #pragma unroll
    for (int t = 0; t < 8; t++) {
        int idx = tid + t*256;
        int r = idx >> 4, qi = idx & 15;
        int rg = m0 + r;
        float4 v = make_float4(0.f,0.f,0.f,0.f);
        if (rg < NP)
            v = *(const float4*)(g_ts + (size_t)rg*DD + kb*64 + qi*4);
        *(float4*)(ts_s + r*64 + qi*4) = v;
    }
    __syncthreads();

    int r0g = tid >> 3;
    int qf  = tid & 7;
    uint32_t dstoff[4];
    const uint32_t* bS[4];
    int hrow[4]; int hvalid[4];
    #pragma unroll
    for (int t = 0; t < 4; t++) {
        int r = r0g + t*32;
        dstoff[t] = (uint32_t)(r*128) + (uint32_t)((qf ^ (r & 7)) << 4);
        bS[t] = BT + (size_t)r*KBIL + kb*4096 + half*2048 + qf*4;
        hrow[t] = m0 + r;
        hvalid[t] = (m0 + r) < NP;
    }
    int icol0 = kb*64 + half*32;

    int lg = lane >> 3, l7 = lane & 7;
    int arow = wm*64 + ((lg & 1) << 3) + l7;
    int brow = wn*32 + ((lg >> 1) << 3) + l7;
    uint32_t acol[4], bcol[4];
    #pragma unroll
    for (int ks = 0; ks < 4; ks++) {
        acol[ks] = (uint32_t)(((((ks<<1) + (lg>>1)) ^ (arow & 7))) << 4);
        bcol[ks] = (uint32_t)(((((ks<<1) + (lg&1))  ^ (brow & 7))) << 4);
    }
    uint32_t aBase = sbase + (uint32_t)(arow*128);
    uint32_t bBase = sbase + 16384u + (uint32_t)(brow*128);

    float acc[4][4][4];
    #pragma unroll
    for (int i = 0; i < 4; i++)
        #pragma unroll
        for (int j = 0; j < 4; j++)
            #pragma unroll
            for (int k = 0; k < 4; k++) acc[i][j][k] = 0.f;

    float hv[4];
    float4 av[4];
    auto issueB = [&](int kc, int buf) {
        uint32_t off = sbase + (uint32_t)(buf*32768) + 16384u;
        int ko = kc*32;
        #pragma unroll
        for (int t = 0; t < 4; t++)
            cpa16(off + dstoff[t], bS[t] + ko, 16u);
        CP_COMMIT();
    };
    auto gatherA = [&](int kc) {
        if ((kc & 1) == 0) {
            int icol = icol0 + (kc >> 1);
            #pragma unroll
            for (int t = 0; t < 4; t++)
                hv[t] = hvalid[t] ? g_hs[(size_t)hrow[t]*DD + icol] : 0.f;
        }
        int j0 = ((kc & 1) << 5) + qf*4;
        #pragma unroll
        for (int t = 0; t < 4; t++) {
            int r = r0g + t*32;
            float4 tv = *(const float4*)(ts_s + r*64 + j0);
            av[t] = make_float4(hv[t]*tv.x, hv[t]*tv.y, hv[t]*tv.z, hv[t]*tv.w);
        }
    };
    auto storeA = [&](int buf) {
        uint32_t off = sbase + (uint32_t)(buf*32768);
        #pragma unroll
        for (int t = 0; t < 4; t++)
            sts128(off + dstoff[t],
                   f2tf32(av[t].x), f2tf32(av[t].y), f2tf32(av[t].z), f2tf32(av[t].w));
    };
    auto compute = [&](int buf) {
        uint32_t ab = aBase + (uint32_t)(buf*32768);
        uint32_t bb = bBase + (uint32_t)(buf*32768);
        #pragma unroll
        for (int ks = 0; ks < 4; ks++) {
            uint32_t bfr[4][2];
            #pragma unroll
            for (int ntp = 0; ntp < 2; ntp++)
                ldsm4(bb + (uint32_t)(ntp*2048) + bcol[ks],
                      bfr[2*ntp][0], bfr[2*ntp][1], bfr[2*ntp+1][0], bfr[2*ntp+1][1]);
            #pragma unroll
            for (int mt = 0; mt < 4; mt++) {
                uint32_t a0, a1, a2, a3;
                ldsm4(ab + (uint32_t)(mt*2048) + acol[ks], a0, a1, a2, a3);
                #pragma unroll
                for (int nt = 0; nt < 4; nt++)
                    mma_tf32(acc[mt][nt], a0, a1, a2, a3, bfr[nt][0], bfr[nt][1]);
            }
        }
    };

    issueB(0, 0);
    gatherA(0);
    for (int kc = 0; kc < 64; kc++) {
        int buf = kc & 1;
        storeA(buf);
        CP_WAIT0();
        __syncthreads();
        if (kc + 1 < 64) { issueB(kc + 1, buf ^ 1); gatherA(kc + 1); }
        compute(buf);
    }

    int eg = lane >> 2, ec = lane & 3;
    #pragma unroll
    for (int mt = 0; mt < 4; mt++) {
        int r0 = m0 + wm*64 + mt*16 + eg;
        int r1 = r0 + 8;
        #pragma unroll
        for (int nt = 0; nt < 4; nt++) {
            int c0 = wn*32 + nt*8 + 2*ec;
            #pragma unroll
            for (int u = 0; u < 2; u++) {
                int col = c0 + u;
                if (col < LL) {
                    if (r0 < NP) g_part[((size_t)slot*NP + r0)*LL + col] = acc[mt][nt][u];
                    if (r1 < NP) g_part[((size_t)slot*NP + r1)*LL + col] = acc[mt][nt][2+u];
                }
            }
        }
    }
}

// ================= transpose -> tf32 =================
__global__ void ktrans(const float* __restrict__ in, int R, int C, int Cout,
                       uint32_t* __restrict__ out)
{
    __shared__ float t[32][33];
    int c0 = blockIdx.x*32, r0 = blockIdx.y*32;
    int tx = threadIdx.x, ty = threadIdx.y;
    #pragma unroll
    for (int j = 0; j < 32; j += 8) {
        int r = r0 + ty + j, c = c0 + tx;
        t[ty+j][tx] = (r < R && c < C) ? in[(size_t)r*C + c] : 0.f;
    }
    __syncthreads();
    #pragma unroll
    for (int j = 0; j < 32; j += 8) {
        int c = c0 + ty + j, r = r0 + tx;
        if (c < Cout && r < R) out[(size_t)c*R + r] = f2tf32(t[tx][ty+j]);
    }
}

// dual transpose (head/tail): z selects (in,out) pair; square shapes R x C
__global__ void ktrans2(const float* __restrict__ inA, uint32_t* __restrict__ outA,
                        const float* __restrict__ inB, uint32_t* __restrict__ outB,
                        int R, int C)
{
    __shared__ float t[32][33];
    int c0 = blockIdx.x*32, r0 = blockIdx.y*32;
    const float* in = blockIdx.z ? inB : inA;
    uint32_t* out = blockIdx.z ? outB : outA;
    int tx = threadIdx.x, ty = threadIdx.y;
    #pragma unroll
    for (int j = 0; j < 32; j += 8)
        t[ty+j][tx] = in[(size_t)(r0+ty+j)*C + c0 + tx];
    __syncthreads();
    #pragma unroll
    for (int j = 0; j < 32; j += 8)
        out[(size_t)(c0+ty+j)*R + r0 + tx] = f2tf32(t[tx][ty+j]);
}

__global__ void ktransB(const float* __restrict__ in, uint32_t* __restrict__ out)
{
    __shared__ float t[32][33];
    int d0 = blockIdx.x*32, c0 = blockIdx.y*32, n = blockIdx.z;
    int tx = threadIdx.x, ty = threadIdx.y;
    const float* inb = in + (size_t)n*CC*DD;
    uint32_t* outb = out + (size_t)n*DD*CC;
    #pragma unroll
    for (int j = 0; j < 32; j += 8)
        t[ty+j][tx] = inb[(size_t)(c0+ty+j)*DD + d0 + tx];
    __syncthreads();
    #pragma unroll
    for (int j = 0; j < 32; j += 8)
        outb[(size_t)(d0+ty+j)*CC + c0 + tx] = f2tf32(t[tx][ty+j]);
}

// ---------------- K1: gather ----------------
__global__ void k_gather(const float* __restrict__ seq, const float* __restrict__ att,
                         const int* __restrict__ ms)
{
    int ne = blockIdx.x;
    int n  = ne / EE;
    int tid = threadIdx.x;
    for (int m = 0; m < MMENT; m++) {
        int pos = ms[ne*MMENT + m] + 1;
        const float* srow = seq + ((size_t)n*CC + pos)*DD;
        float* erow = g_eemb + ((size_t)ne*MMENT + m)*DD;
        for (int d = tid; d < DD; d += blockDim.x) erow[d] = srow[d];
        float* arow = g_eatt + ((size_t)ne*MMENT + m)*CC;
        for (int c = tid; c < CC; c += blockDim.x) {
            float s = 0.f;
            #pragma unroll
            for (int h = 0; h < HH; h++)
                s += att[(((size_t)n*HH + h)*CC + pos)*CC + c];
            arow[c] = s * (1.0f/HH);
        }
    }
    __syncthreads();
    for (int d = tid; d < DD; d += blockDim.x) {
        float x0 = g_eemb[((size_t)ne*MMENT+0)*DD+d];
        float x1 = g_eemb[((size_t)ne*MMENT+1)*DD+d];
        float x2 = g_eemb[((size_t)ne*MMENT+2)*DD+d];
        float x3 = g_eemb[((size_t)ne*MMENT+3)*DD+d];
        float mx = fmaxf(fmaxf(x0,x1), fmaxf(x2,x3));
        float s = expf(x0-mx)+expf(x1-mx)+expf(x2-mx)+expf(x3-mx);
        g_glob[(size_t)ne*DD + d] = mx + logf(s);
    }
}

// ---------------- K3: edge ----------------
__global__ void k_edge(const float* __restrict__ bm)
{
    int idx = blockIdx.x*blockDim.x + threadIdx.x;
    const int total = NN*EE*EE*DD;
    if (idx >= total) return;
    int d = idx % DD;
    int v = (idx / DD) % EE;
    int u = (idx / (DD*EE)) % EE;
    int n = idx / (DD*EE*EE);
    float val = g_A[((size_t)n*EE+u)*DD+d] + g_B[((size_t)n*EE+v)*DD+d] + bm[d];
    g_edge[idx] = fmaxf(val, 0.f);
}

// ---------------- K4: pair attention ----------------
__global__ void k_pair(const int* __restrict__ hts, const int* __restrict__ ms)
{
    int r = blockIdx.x;
    int n = r / PP;
    int h = hts[r*2 + 0];
    int t = hts[r*2 + 1];
    __shared__ int   s_ph[MMENT], s_pt[MMENT];
    __shared__ float s_phatt[MMENT], s_ptatt[MMENT];
    __shared__ float s_red[256];
    int tid = threadIdx.x;
    if (tid < MMENT) {
        s_ph[tid] = ms[((size_t)n*EE+h)*MMENT + tid] + 1;
        s_pt[tid] = ms[((size_t)n*EE+t)*MMENT + tid] + 1;
    }
    __syncthreads();
    if (tid < 2*MMENT) {
        int m2 = tid & (MMENT-1);
        float s = 0.f;
        if (tid < MMENT) {
            for (int m1 = 0; m1 < MMENT; m1++)
                s += g_eatt[((size_t)(n*EE+h)*MMENT+m1)*CC + s_pt[m2]];
            s_phatt[m2] = s * (1.f/MMENT);
        } else {
            for (int m1 = 0; m1 < MMENT; m1++)
                s += g_eatt[((size_t)(n*EE+t)*MMENT+m1)*CC + s_ph[m2]];
            s_ptatt[m2] = s * (1.f/MMENT);
        }
    }
    __syncthreads();
    if (tid == 0) {
        float sh = 1e-5f, st = 1e-5f;
        for (int m = 0; m < MMENT; m++) { sh += s_phatt[m]; st += s_ptatt[m]; }
        float ih = 1.f/sh, it = 1.f/st;
        for (int m = 0; m < MMENT; m++) { s_phatt[m] *= ih; s_ptatt[m] *= it; }
    }
    __syncthreads();
    for (int d = tid; d < DD; d += blockDim.x) {
        float nh = 0.f, nt = 0.f;
        #pragma unroll
        for (int m = 0; m < MMENT; m++) {
            nh += s_ptatt[m]*g_eemb[((size_t)(n*EE+h)*MMENT+m)*DD + d];
            nt += s_phatt[m]*g_eemb[((size_t)(n*EE+t)*MMENT+m)*DD + d];
        }
        uint32_t nh32 = f2tf32(nh), nt32 = f2tf32(nt);
        g_hcat32[(size_t)r*DIM3 + d] = nh32;
        g_tcat32[(size_t)r*DIM3 + d] = nt32;
        g_q32[(size_t)r*DIM2 + d]      = nh32;
        g_q32[(size_t)r*DIM2 + DD + d] = nt32;
    }
    float local = 0.f;
    for (int c = tid; c < CC; c += blockDim.x) {
        float na = 0.f, ta = 0.f;
        #pragma unroll
        for (int m = 0; m < MMENT; m++) {
            na += s_ptatt[m]*g_eatt[((size_t)(n*EE+h)*MMENT+m)*CC + c];
            ta += s_phatt[m]*g_eatt[((size_t)(n*EE+t)*MMENT+m)*CC + c];
        }
        float v = na*ta;
        g_pa[(size_t)r*CC + c] = v;
        local += v;
    }
    s_red[tid] = local;
    __syncthreads();
    for (int off = 128; off > 0; off >>= 1) {
        if (tid < off) s_red[tid] += s_red[tid+off];
        __syncthreads();
    }
    float inv = 1.f/(s_red[0] + 1e-5f);
    for (int c = tid; c < CC; c += blockDim.x)
        g_pa32[(size_t)r*CC + c] = f2tf32(g_pa[(size_t)r*CC + c]*inv);
}

// ---------------- fp32 SGEMM (Wm1+Wm2 merged) ----------------
__global__ void __launch_bounds__(256) sgemm(
    int M, int Nn, int Kc, int S,
    const float* __restrict__ A, int lda,
    const float* __restrict__ B, const float* __restrict__ B2, int ldb,
    float* __restrict__ part)
{
    int z = blockIdx.z;
    int s = z % S, b = z / S;
    const float* Ab = A + (size_t)s*Kc;
    const float* Bb = ((b && B2) ? B2 : B) + (size_t)s*Kc*ldb;
    int m0 = blockIdx.y*128, n0 = blockIdx.x*128;
    __shared__ float As[8][128];
    __shared__ float Bs[8][128];
    int tid = threadIdx.x;
    int arow = tid >> 1, ak = (tid & 1)*4;
    int bk = tid >> 5,  bn = (tid & 31)*4;
    int tx = tid & 15,  ty = tid >> 4;
    float acc[8][8];
    #pragma unroll
    for (int i = 0; i < 8; i++)
        #pragma unroll
        for (int j = 0; j < 8; j++) acc[i][j] = 0.f;
    for (int k0 = 0; k0 < Kc; k0 += 8) {
        float4 av = make_float4(0.f,0.f,0.f,0.f);
        if (m0 + arow < M)
            av = *(const float4*)(Ab + (size_t)(m0+arow)*lda + k0 + ak);
        float4 bvv = *(const float4*)(Bb + (size_t)(k0+bk)*ldb + n0 + bn);
        __syncthreads();
        As[ak+0][arow] = av.x; As[ak+1][arow] = av.y;
        As[ak+2][arow] = av.z; As[ak+3][arow] = av.w;
        *(float4*)&Bs[bk][bn] = bvv;
        __syncthreads();
        #pragma unroll
        for (int kk = 0; kk < 8; kk++) {
            float a[8], bb[8];
            *(float4*)(a)    = *(const float4*)&As[kk][ty*8];
            *(float4*)(a+4)  = *(const float4*)&As[kk][ty*8+4];
            *(float4*)(bb)   = *(const float4*)&Bs[kk][tx*8];
            *(float4*)(bb+4) = *(const float4*)&Bs[kk][tx*8+4];
            #pragma unroll
            for (int i = 0; i < 8; i++)
                #pragma unroll
                for (int j = 0; j < 8; j++)
                    acc[i][j] += a[i]*bb[j];
        }
    }
    float* pbase = part + ((size_t)z*M)*Nn;
    #pragma unroll
    for (int i = 0; i < 8; i++) {
        int r = m0 + ty*8 + i;
        if (r < M) {
            float* prow = pbase + (size_t)r*Nn + n0 + tx*8;
            *(float4*)(prow)   = make_float4(acc[i][0],acc[i][1],acc[i][2],acc[i][3]);
            *(float4*)(prow+4) = make_float4(acc[i][4],acc[i][5],acc[i][6],acc[i][7]);
        }
    }
}

// merged Wm reduce: sums 12 slots each for gA and gB
__global__ void k_redwm()
{
    int idx = blockIdx.x*blockDim.x + threadIdx.x;
    const int total = NN*EE*DD;
    if (idx >= total) return;
    float a = 0.f, b = 0.f;
    #pragma unroll
    for (int s = 0; s < 12; s++) {
        a += g_partm[(size_t)s*total + idx];
        b += g_partm[(size_t)(s+12)*total + idx];
    }
    g_A[idx] = a;
    g_B[idx] = b;
}

__global__ void reduce_ep(const float* __restrict__ part, int S, int Mtot, int Nn,
                          const float* __restrict__ bias, int dorelu, int tf32out,
                          float* __restrict__ dst1, int ld1,
                          float* __restrict__ dst2, int ld2)
{
    int idx = blockIdx.x*blockDim.x + threadIdx.x;
    if (idx >= Mtot*Nn) return;
    int r = idx / Nn, c = idx % Nn;
    float v = 0.f;
    for (int s = 0; s < S; s++)
        v += part[((size_t)s*Mtot + r)*Nn + c];
    if (bias) v += bias[c];
    if (dorelu) v = fmaxf(v, 0.f);
    if (tf32out) {
        uint32_t u = f2tf32(v);
        ((uint32_t*)dst1)[(size_t)r*ld1 + c] = u;
        if (dst2) ((uint32_t*)dst2)[(size_t)r*ld2 + c] = u;
    } else {
        dst1[(size_t)r*ld1 + c] = v;
        if (dst2) dst2[(size_t)r*ld2 + c] = v;
    }
}

// ---------------- grouped score ----------------
__global__ void __launch_bounds__(256) k_score(const float* __restrict__ qW)
{
    extern __shared__ float sm[];
    int e = blockIdx.x, kk = blockIdx.y, n = blockIdx.z;
    int tid = threadIdx.x;
    bool strided = (kk == 1) || (kk == 3);
    bool grouph  = (kk == 0) || (kk == 3);
    for (int idx = tid; idx < EE*DD; idx += 256) {
        int v = idx / DD, d = idx % DD;
        size_t off = strided ? (((size_t)(n*EE + v)*EE + e))*DD + d
                             : (((size_t)(n*EE + e)*EE + v))*DD + d;
        sm[idx] = g_edge[off];
    }
    __syncthreads();
    int wid = tid >> 5, lane = tid & 31;
    for (int jj = wid; jj < EE-1; jj += 8) {
        int p = group_pair(n, e, jj, grouph);
        const float* qrow = qW + (size_t)p*DIM4 + kk*DD;
        float q[24];
        #pragma unroll
        for (int u = 0; u < 24; u++) q[u] = qrow[lane + 32*u];
        for (int v = 0; v < EE; v++) {
            const float* smv = sm + v*DD;
            float acc = 0.f;
            #pragma unroll
            for (int u = 0; u < 24; u++) acc += q[u]*smv[lane + 32*u];
            #pragma unroll
            for (int o = 16; o; o >>= 1) acc += __shfl_down_sync(0xffffffffu, acc, o);
            if (lane == 0) g_spart[((size_t)kk*NP + p)*EE + v] = acc;
        }
    }
}

// ---------------- softmax ----------------
__global__ void k_softmax(const int* __restrict__ hts, const float* __restrict__ battp)
{
    int p = blockIdx.x;
    int lane = threadIdx.x;
    int h = hts[p*2], t = hts[p*2+1];
    float s = -1e38f;
    if (lane < EE) {
        s = g_spart[((size_t)0*NP+p)*EE+lane] + g_spart[((size_t)1*NP+p)*EE+lane]
          + g_spart[((size_t)2*NP+p)*EE+lane] + g_spart[((size_t)3*NP+p)*EE+lane]
          + battp[0];
        if (lane == h || lane == t) s = NEGV;
    }
    float mx = s;
    #pragma unroll
    for (int o = 16; o; o >>= 1) mx = fmaxf(mx, __shfl_xor_sync(0xffffffffu, mx, o));
    float ex = (lane < EE) ? expf(s - mx) : 0.f;
    float sum = ex;
    #pragma unroll
    for (int o = 16; o; o >>= 1) sum += __shfl_xor_sync(0xffffffffu, sum, o);
    if (lane < EE) g_aw[(size_t)p*EE + lane] = ex/sum;
}

// ---------------- grouped path ----------------
__global__ void __launch_bounds__(256) k_pathg()
{
    extern __shared__ float sm[];
    float* aws = sm + EE*DD;
    int e = blockIdx.x, kk = blockIdx.y, n = blockIdx.z;
    int tid = threadIdx.x;
    bool strided = (kk == 1) || (kk == 3);
    bool grouph  = (kk == 0) || (kk == 3);
    for (int idx = tid; idx < EE*DD; idx += 256) {
        int v = idx / DD, d = idx % DD;
        size_t off = strided ? (((size_t)(n*EE + v)*EE + e))*DD + d
                             : (((size_t)(n*EE + e)*EE + v))*DD + d;
        sm[idx] = g_edge[off];
    }
    for (int idx = tid; idx < 19*EE; idx += 256) {
        int jj = idx / EE, v = idx % EE;
        int p = group_pair(n, e, jj, grouph);
        aws[idx] = g_aw[(size_t)p*EE + v];
    }
    __syncthreads();
    for (int idx = tid; idx < 19*DD; idx += 256) {
        int jj = idx / DD, d = idx % DD;
        float acc = 0.f;
        #pragma unroll
        for (int v = 0; v < EE; v++)
            acc += aws[jj*EE + v]*sm[v*DD + d];
        int p = group_pair(n, e, jj, grouph);
        g_praw32[(size_t)p*DIM4 + kk*DD + d] = f2tf32(acc);
    }
}

__global__ void k_bilred(const float* __restrict__ bbil, float* __restrict__ out)
{
    int idx = blockIdx.x*blockDim.x + threadIdx.x;
    if (idx >= NP*LL) return;
    int r = idx / LL, l = idx % LL;
    float v = bbil[l];
    #pragma unroll
    for (int k = 0; k < 24; k++)
        v += g_part[((size_t)k*NP + r)*LL + l];
    out[idx] = v;
}

// ---------------- launcher ----------------
static void* symaddr(const void* sym)
{
    void* p = nullptr;
    cudaGetSymbolAddress(&p, sym);
    return p;
}

extern "C" void kernel_launch(void* const* d_in, const int* in_sizes, int n_in,
                              void* d_out, int out_size)
{
    const float* seq   = (const float*)d_in[0];
    const float* att   = (const float*)d_in[1];
    const int*   ms    = (const int*)  d_in[2];
    const int*   hts   = (const int*)  d_in[3];
    const float* Wm1   = (const float*)d_in[4];
    const float* Wm2   = (const float*)d_in[5];
    const float* bm    = (const float*)d_in[6];
    const float* Watt  = (const float*)d_in[7];
    const float* batt  = (const float*)d_in[8];
    const float* Wpath = (const float*)d_in[9];
    const float* bpath = (const float*)d_in[10];
    const float* Whead = (const float*)d_in[11];
    const float* bhead = (const float*)d_in[12];
    const float* Wtail = (const float*)d_in[13];
    const float* btail = (const float*)d_in[14];
    const float* Wbil  = (const float*)d_in[15];
    const float* bbil  = (const float*)d_in[16];
    float* out = (float*)d_out;

    float*    glob   = (float*)symaddr(g_glob);
    float*    qW     = (float*)symaddr(g_qW);
    float*    hs     = (float*)symaddr(g_hs);
    float*    ts     = (float*)symaddr(g_ts);
    float*    part   = (float*)symaddr(g_part);
    float*    partm  = (float*)symaddr(g_partm);
    uint32_t* pa32   = (uint32_t*)symaddr(g_pa32);
    uint32_t* seqT32 = (uint32_t*)symaddr(g_seqT32);
    uint32_t* q32    = (uint32_t*)symaddr(g_q32);
    uint32_t* hcat32 = (uint32_t*)symaddr(g_hcat32);
    uint32_t* tcat32 = (uint32_t*)symaddr(g_tcat32);
    uint32_t* praw32 = (uint32_t*)symaddr(g_praw32);
    uint32_t* wTatt  = (uint32_t*)symaddr(g_wT_att32);
    uint32_t* wTpath = (uint32_t*)symaddr(g_wT_path32);
    uint32_t* wThead = (uint32_t*)symaddr(g_wT_head32);
    uint32_t* wTtail = (uint32_t*)symaddr(g_wT_tail32);
    uint32_t* wTbil  = (uint32_t*)symaddr(g_wT_bil32);

    const int SMEM_WG = 98304;
    const int SMEM_WB = 98304;
    const int SMEM_SC = EE*DD*4;
    const int SMEM_PG = EE*DD*4 + 19*EE*4;
    cudaFuncSetAttribute(wgemm,  cudaFuncAttributeMaxDynamicSharedMemorySize, SMEM_WG);
    cudaFuncSetAttribute(wbil,   cudaFuncAttributeMaxDynamicSharedMemorySize, SMEM_WB);
    cudaFuncSetAttribute(k_score, cudaFuncAttributeMaxDynamicSharedMemorySize, SMEM_SC);
    cudaFuncSetAttribute(k_pathg, cudaFuncAttributeMaxDynamicSharedMemorySize, SMEM_PG);

    // --- ordered so launch index 3 (ncu capture slot) is the qW wgemm ---
    k_gather<<<NN*EE, 256>>>(seq, att, ms);                                        // 0
    k_pair<<<NP, 256>>>(hts, ms);                                                  // 1
    ktrans<<<dim3(DIM4/32, DIM2/32), dim3(32,8)>>>(Watt, DIM2, DIM4, DIM4, wTatt); // 2
    // 3: qW = q @ Watt (tf32 mma) <-- ncu profiles this
    wgemm<<<dim3(24,12,1), 256, SMEM_WG>>>(NP, 48, 1,
        q32, DIM2, 0, wTatt, DIM2, 0, nullptr, nullptr,
        qW, DIM4, 0, nullptr, nullptr, 0, 0,
        nullptr, nullptr, 0, 0, nullptr, 0, 0);

    // Wm1+Wm2 merged (fp32, split-K 12 each) -> merged reduce
    sgemm<<<dim3(6,1,24), 256>>>(NN*EE, DD, 64, 12, glob, DD, Wm1, Wm2, DD, partm);
    k_redwm<<<(NN*EE*DD+255)/256, 256>>>();
    k_edge<<<(NN*EE*EE*DD+255)/256, 256>>>(bm);

    // rs = pa @ seq (tf32 mma, per-doc batch, direct dual tf32 epilogue)
    ktransB<<<dim3(DD/32, CC/32, NN), dim3(32,8)>>>(seq, seqT32);
    wgemm<<<dim3(6,3,NN), 256, SMEM_WG>>>(PP, 16, 1,
        pa32, CC, (long long)PP*CC, seqT32, CC, (long long)DD*CC, nullptr, nullptr,
        (float*)(hcat32 + DD), DIM3, (long long)PP*DIM3, nullptr,
        (float*)(tcat32 + DD), DIM3, (long long)PP*DIM3,
        nullptr, nullptr, 0, 1, nullptr, 0, 0);

    // grouped score -> softmax -> grouped path
    k_score<<<dim3(EE,4,NN), 256, SMEM_SC>>>(qW);
    k_softmax<<<NP, 32>>>(hts, batt);
    k_pathg<<<dim3(EE,4,NN), 256, SMEM_PG>>>();

    // path = relu(pathraw @ Wpath + bpath): Sr=4 -> 288 CTAs (2/SM)
    ktrans<<<dim3(DD/32, DIM4/32), dim3(32,8)>>>(Wpath, DIM4, DD, DD, wTpath);
    wgemm<<<dim3(6,12,4), 256, SMEM_WG>>>(NP, 24, 4,
        praw32, DIM4, 0, wTpath, DIM4, 0, nullptr, nullptr,
        nullptr, 0, 0, nullptr, nullptr, 0, 0,
        nullptr, nullptr, 0, 0, part, NP, DD);
    reduce_ep<<<(NP*DD+255)/256, 256>>>(part, 4, NP, DD, bpath, 1, 1,
                                        (float*)(hcat32 + 2*DD), DIM3,
                                        (float*)(tcat32 + 2*DD), DIM3);

    // hs / ts projections: merged batch + Sr=2 partials -> 288 CTAs (2/SM)
    ktrans2<<<dim3(DD/32, DIM3/32, 2), dim3(32,8)>>>(Whead, wThead, Wtail, wTtail,
                                                     DIM3, DD);
    wgemm<<<dim3(6,12,4), 256, SMEM_WG>>>(NP, 36, 2,
        hcat32, DIM3, 0, wThead, DIM3, 0, tcat32, wTtail,
        nullptr, 0, 0, nullptr, nullptr, 0, 0,
        nullptr, nullptr, 0, 0, part, NP, DD);
    reduce_ep<<<(NP*DD+255)/256, 256>>>(part, 2, NP, DD, bhead, 1, 0,
                                        hs, DD, nullptr, 0);
    reduce_ep<<<(NP*DD+255)/256, 256>>>(part + (size_t)2*NP*DD, 2, NP, DD, btail, 1, 0,
                                        ts, DD, nullptr, 0);

    // bilinear head: grid (12, 24), partial slots 0..23
    ktrans<<<dim3(4, KBIL/32), dim3(32,8)>>>(Wbil, KBIL, LL, 128, wTbil);
    wbil<<<dim3(12,24), 256, SMEM_WB>>>(wTbil);
    k_bilred<<<(NP*LL+255)/256, 256>>>(bbil, out);
}

// round 16
// speedup vs baseline: 1.0402x; 1.0377x over previous
#include <cuda_runtime.h>
#include <cstdint>
#include <math.h>

#define NN 4
#define CC 512
#define DD 768
#define HH 12
#define EE 20
#define MMENT 4
#define PP 380
#define NP 1520
#define LL 97
#define DIM2 1536
#define DIM3 2304
#define DIM4 3072
#define KBIL 49152
#define NEGV (-1e30f)

// ---------------- static device scratch ----------------
__device__ float g_eemb[NN*EE*MMENT*DD];
__device__ float g_eatt[NN*EE*MMENT*CC];
__device__ float g_glob[NN*EE*DD];
__device__ float g_A[NN*EE*DD];
__device__ float g_B[NN*EE*DD];
__device__ float g_edge[NN*EE*EE*DD];
__device__ float g_pa[NP*CC];
__device__ float g_qW[NP*DIM4];
__device__ float g_hs[NP*DD];
__device__ float g_ts[NP*DD];
__device__ float g_part[4*NP*DD];
__device__ float g_partm[24*NN*EE*DD];
__device__ float g_spart[4*NP*EE];
__device__ float g_aw[NP*EE];
// tf32 (u32 bit pattern) GEMM operands
__device__ uint32_t g_pa32[NP*CC];
__device__ uint32_t g_seqT32[NN*DD*CC];
__device__ uint32_t g_q32[NP*DIM2];
__device__ uint32_t g_hcat32[NP*DIM3];
__device__ uint32_t g_tcat32[NP*DIM3];
__device__ uint32_t g_praw32[NP*DIM4];
__device__ uint32_t g_wT_att32[DIM4*DIM2];
__device__ uint32_t g_wT_path32[DD*DIM4];
__device__ uint32_t g_wT_head32[DD*DIM3];
__device__ uint32_t g_wT_tail32[DD*DIM3];
__device__ uint32_t g_wT_bil32[128*KBIL];   // rows 97..127 zero

// ---------------- helpers ----------------
__device__ __forceinline__ uint32_t f2tf32(float f) {
    uint32_t r;
    asm("cvt.rna.tf32.f32 %0, %1;" : "=r"(r) : "f"(f));
    return r;
}
__device__ __forceinline__ void mma_tf32(float* d, uint32_t a0, uint32_t a1,
                                         uint32_t a2, uint32_t a3,
                                         uint32_t b0, uint32_t b1)
{
    asm volatile(
        "mma.sync.aligned.m16n8k8.row.col.f32.tf32.tf32.f32 "
        "{%0,%1,%2,%3}, {%4,%5,%6,%7}, {%8,%9}, {%0,%1,%2,%3};"
        : "+f"(d[0]), "+f"(d[1]), "+f"(d[2]), "+f"(d[3])
        : "r"(a0), "r"(a1), "r"(a2), "r"(a3), "r"(b0), "r"(b1));
}
__device__ __forceinline__ void ldsm4(uint32_t addr, uint32_t& a, uint32_t& b,
                                      uint32_t& c, uint32_t& d)
{
    asm volatile("ldmatrix.sync.aligned.m8n8.x4.shared.b16 {%0,%1,%2,%3}, [%4];"
                 : "=r"(a), "=r"(b), "=r"(c), "=r"(d) : "r"(addr));
}
__device__ __forceinline__ void sts128(uint32_t addr, uint32_t x, uint32_t y,
                                       uint32_t z, uint32_t w)
{
    asm volatile("st.shared.v4.b32 [%0], {%1,%2,%3,%4};"
                 :: "r"(addr), "r"(x), "r"(y), "r"(z), "r"(w) : "memory");
}
__device__ __forceinline__ void cpa16(uint32_t dst, const void* src, uint32_t sz)
{
    asm volatile("cp.async.cg.shared.global [%0], [%1], 16, %2;"
                 :: "r"(dst), "l"(src), "r"(sz) : "memory");
}
#define CP_COMMIT() asm volatile("cp.async.commit_group;" ::: "memory")
#define CP_WAIT0()  asm volatile("cp.async.wait_group 0;" ::: "memory")
#define CP_WAIT1()  asm volatile("cp.async.wait_group 1;" ::: "memory")

// pair-index helper
__device__ __forceinline__ int group_pair(int n, int e, int jj, bool grouph)
{
    if (grouph) return n*PP + e*19 + jj;
    int i = jj + (jj >= e);
    return n*PP + i*19 + (e < i ? e : e - 1);
}

// ================ tf32 warp-mma GEMM: 3-stage cp.async pipeline + ldmatrix ================
__global__ void __launch_bounds__(256,2) wgemm(
    int M, int nchunks, int Sr,
    const uint32_t* __restrict__ A, int lda, long long sAb,
    const uint32_t* __restrict__ BT, int ldbt, long long sBTb,
    const uint32_t* __restrict__ A2, const uint32_t* __restrict__ BT2,
    float* __restrict__ dst1, int ld1, long long d1b, float* __restrict__ dst1b,
    float* __restrict__ dst2, int ld2, long long d2b,
    const float* __restrict__ bias, const float* __restrict__ bias2,
    int relu, int tf32out,
    float* __restrict__ part, int Mtot, int Nn)
{
    extern __shared__ float smf[];
    uint32_t sbase = (uint32_t)__cvta_generic_to_shared(smf);
    int tid = threadIdx.x;
    int lane = tid & 31, wid = tid >> 5;
    int wm = wid >> 2, wn = wid & 3;
    int m0 = blockIdx.y*128, n0 = blockIdx.x*128;
    int z = blockIdx.z;
    int s = z % Sr, b = z / Sr;
    const uint32_t* Ause;
    const uint32_t* BTuse;
    float* d1; float* d2;
    const float* biasu;
    if (A2) {
        Ause  = b ? A2  : A;
        BTuse = b ? BT2 : BT;
        d1 = b ? dst1b : dst1;
        d2 = dst2;
        biasu = (b && bias2) ? bias2 : bias;
    } else {
        Ause  = A + (size_t)b*sAb;
        BTuse = BT + (size_t)b*sBTb;
        d1 = dst1 ? dst1 + (size_t)b*d1b : nullptr;
        d2 = dst2 ? dst2 + (size_t)b*d2b : nullptr;
        biasu = bias;
    }
    int kbase = s*nchunks*32;

    int r0g = tid >> 3;
    int qf  = tid & 7;
    uint32_t dstoff[4];
    const uint32_t* aS[4]; uint32_t aSz[4];
    const uint32_t* bS[4];
    #pragma unroll
    for (int t = 0; t < 4; t++) {
        int r = r0g + t*32;
        dstoff[t] = (uint32_t)(r*128) + (uint32_t)((qf ^ (r & 7)) << 4);
        int rm = m0 + r;
        int rcl = rm < M ? rm : (M-1);
        aS[t]  = Ause + (size_t)rcl*lda + kbase + qf*4;
        aSz[t] = (rm < M) ? 16u : 0u;
        bS[t]  = BTuse + (size_t)(n0 + r)*ldbt + kbase + qf*4;
    }

    int lg = lane >> 3, l7 = lane & 7;
    int arow = wm*64 + ((lg & 1) << 3) + l7;
    int brow = wn*32 + ((lg >> 1) << 3) + l7;
    uint32_t acol[4], bcol[4];
    #pragma unroll
    for (int ks = 0; ks < 4; ks++) {
        acol[ks] = (uint32_t)(((((ks<<1) + (lg>>1)) ^ (arow & 7))) << 4);
        bcol[ks] = (uint32_t)(((((ks<<1) + (lg&1))  ^ (brow & 7))) << 4);
    }
    uint32_t aBase = sbase + (uint32_t)(arow*128);
    uint32_t bBase = sbase + 16384u + (uint32_t)(brow*128);

    float acc[4][4][4];
    #pragma unroll
    for (int i = 0; i < 4; i++)
        #pragma unroll
        for (int j = 0; j < 4; j++)
            #pragma unroll
            for (int k = 0; k < 4; k++) acc[i][j][k] = 0.f;

    auto issue = [&](int kc, int st) {
        uint32_t off = sbase + (uint32_t)(st*32768);
        int ko = kc*32;
        #pragma unroll
        for (int t = 0; t < 4; t++) {
            cpa16(off + dstoff[t], aS[t] + ko, aSz[t]);
            cpa16(off + 16384u + dstoff[t], bS[t] + ko, 16u);
        }
        CP_COMMIT();
    };
    auto compute = [&](int st) {
        uint32_t ab = aBase + (uint32_t)(st*32768);
        uint32_t bb = bBase + (uint32_t)(st*32768);
        #pragma unroll
        for (int ks = 0; ks < 4; ks++) {
            uint32_t bfr[4][2];
            #pragma unroll
            for (int ntp = 0; ntp < 2; ntp++)
                ldsm4(bb + (uint32_t)(ntp*2048) + bcol[ks],
                      bfr[2*ntp][0], bfr[2*ntp][1], bfr[2*ntp+1][0], bfr[2*ntp+1][1]);
            #pragma unroll
            for (int mt = 0; mt < 4; mt++) {
                uint32_t a0, a1, a2, a3;
                ldsm4(ab + (uint32_t)(mt*2048) + acol[ks], a0, a1, a2, a3);
                #pragma unroll
                for (int nt = 0; nt < 4; nt++)
                    mma_tf32(acc[mt][nt], a0, a1, a2, a3, bfr[nt][0], bfr[nt][1]);
            }
        }
    };

    issue(0, 0);
    if (nchunks > 1) issue(1, 1);
    int st = 0;
    for (int kc = 0; kc < nchunks; kc++) {
        if (kc + 1 < nchunks) CP_WAIT1(); else CP_WAIT0();
        __syncthreads();
        if (kc + 2 < nchunks) {
            int st2 = st + 2; if (st2 >= 3) st2 -= 3;
            issue(kc + 2, st2);
        }
        compute(st);
        st = (st == 2) ? 0 : st + 1;
    }

    int eg = lane >> 2, ec = lane & 3;
    #pragma unroll
    for (int mt = 0; mt < 4; mt++) {
        int r0 = m0 + wm*64 + mt*16 + eg;
        int r1 = r0 + 8;
        #pragma unroll
        for (int nt = 0; nt < 4; nt++) {
            int c0 = n0 + wn*32 + nt*8 + 2*ec;
            if (part) {
                float* p0 = part + ((size_t)z*Mtot + r0)*Nn + c0;
                float* p1 = part + ((size_t)z*Mtot + r1)*Nn + c0;
                if (r0 < M) { p0[0] = acc[mt][nt][0]; p0[1] = acc[mt][nt][1]; }
                if (r1 < M) { p1[0] = acc[mt][nt][2]; p1[1] = acc[mt][nt][3]; }
            } else {
                float b0 = biasu ? biasu[c0] : 0.f;
                float b1 = biasu ? biasu[c0+1] : 0.f;
                float v0 = acc[mt][nt][0] + b0, v1 = acc[mt][nt][1] + b1;
                float v2 = acc[mt][nt][2] + b0, v3 = acc[mt][nt][3] + b1;
                if (relu) { v0=fmaxf(v0,0.f); v1=fmaxf(v1,0.f); v2=fmaxf(v2,0.f); v3=fmaxf(v3,0.f); }
                if (tf32out) {
                    uint32_t u0 = f2tf32(v0), u1 = f2tf32(v1), u2 = f2tf32(v2), u3 = f2tf32(v3);
                    if (r0 < M) {
                        ((uint32_t*)d1)[(size_t)r0*ld1 + c0] = u0;
                        ((uint32_t*)d1)[(size_t)r0*ld1 + c0+1] = u1;
                        if (d2) { ((uint32_t*)d2)[(size_t)r0*ld2 + c0] = u0;
                                  ((uint32_t*)d2)[(size_t)r0*ld2 + c0+1] = u1; }
                    }
                    if (r1 < M) {
                        ((uint32_t*)d1)[(size_t)r1*ld1 + c0] = u2;
                        ((uint32_t*)d1)[(size_t)r1*ld1 + c0+1] = u3;
                        if (d2) { ((uint32_t*)d2)[(size_t)r1*ld2 + c0] = u2;
                                  ((uint32_t*)d2)[(size_t)r1*ld2 + c0+1] = u3; }
                    }
                } else {
                    if (r0 < M) {
                        d1[(size_t)r0*ld1 + c0] = v0; d1[(size_t)r0*ld1 + c0+1] = v1;
                        if (d2) { d2[(size_t)r0*ld2 + c0] = v0; d2[(size_t)r0*ld2 + c0+1] = v1; }
                    }
                    if (r1 < M) {
                        d1[(size_t)r1*ld1 + c0] = v2; d1[(size_t)r1*ld1 + c0+1] = v3;
                        if (d2) { d2[(size_t)r1*ld2 + c0] = v2; d2[(size_t)r1*ld2 + c0+1] = v3; }
                    }
                }
            }
        }
    }
}

// ===== bilinear: grid (12 m-tiles, 24 slots). slot = kb*2 + half; 64 chunks each. =====
__global__ void __launch_bounds__(256,2) wbil(const uint32_t* __restrict__ BT)
{
    extern __shared__ float smf[];
    uint32_t sbase = (uint32_t)__cvta_generic_to_shared(smf);
    float* ts_s = smf + 16384;           // [128][64]
    int tid = threadIdx.x;
    int lane = tid & 31, wid = tid >> 5;
    int wm = wid >> 2, wn = wid & 3;
    int m0 = blockIdx.x*128;
    int slot = blockIdx.y;
    int kb = slot >> 1, half = slot & 1;

    #pragma unroll
    for (int t = 0; t < 8; t++) {
        int idx = tid + t*256;
        int r = idx >> 4, qi = idx & 15;
        int rg = m0 + r;
        float4 v = make_float4(0.f,0.f,0.f,0.f);
        if (rg < NP)
            v = *(const float4*)(g_ts + (size_t)rg*DD + kb*64 + qi*4);
        *(float4*)(ts_s + r*64 + qi*4) = v;
    }
    __syncthreads();

    int r0g = tid >> 3;
    int qf  = tid & 7;
    uint32_t dstoff[4];
    const uint32_t* bS[4];
    int hrow[4]; int hvalid[4];
    #pragma unroll
    for (int t = 0; t < 4; t++) {
        int r = r0g + t*32;
        dstoff[t] = (uint32_t)(r*128) + (uint32_t)((qf ^ (r & 7)) << 4);
        bS[t] = BT + (size_t)r*KBIL + kb*4096 + half*2048 + qf*4;
        hrow[t] = m0 + r;
        hvalid[t] = (m0 + r) < NP;
    }
    int icol0 = kb*64 + half*32;

    int lg = lane >> 3, l7 = lane & 7;
    int arow = wm*64 + ((lg & 1) << 3) + l7;
    int brow = wn*32 + ((lg >> 1) << 3) + l7;
    uint32_t acol[4], bcol[4];
    #pragma unroll
    for (int ks = 0; ks < 4; ks++) {
        acol[ks] = (uint32_t)(((((ks<<1) + (lg>>1)) ^ (arow & 7))) << 4);
        bcol[ks] = (uint32_t)(((((ks<<1) + (lg&1))  ^ (brow & 7))) << 4);
    }
    uint32_t aBase = sbase + (uint32_t)(arow*128);
    uint32_t bBase = sbase + 16384u + (uint32_t)(brow*128);

    float acc[4][4][4];
    #pragma unroll
    for (int i = 0; i < 4; i++)
        #pragma unroll
        for (int j = 0; j < 4; j++)
            #pragma unroll
            for (int k = 0; k < 4; k++) acc[i][j][k] = 0.f;

    float hv[4];
    float4 av[4];
    auto issueB = [&](int kc, int buf) {
        uint32_t off = sbase + (uint32_t)(buf*32768) + 16384u;
        int ko = kc*32;
        #pragma unroll
        for (int t = 0; t < 4; t++)
            cpa16(off + dstoff[t], bS[t] + ko, 16u);
        CP_COMMIT();
    };
    auto gatherA = [&](int kc) {
        if ((kc & 1) == 0) {
            int icol = icol0 + (kc >> 1);
            #pragma unroll
            for (int t = 0; t < 4; t++)
                hv[t] = hvalid[t] ? g_hs[(size_t)hrow[t]*DD + icol] : 0.f;
        }
        int j0 = ((kc & 1) << 5) + qf*4;
        #pragma unroll
        for (int t = 0; t < 4; t++) {
            int r = r0g + t*32;
            float4 tv = *(const float4*)(ts_s + r*64 + j0);
            av[t] = make_float4(hv[t]*tv.x, hv[t]*tv.y, hv[t]*tv.z, hv[t]*tv.w);
        }
    };
    auto storeA = [&](int buf) {
        uint32_t off = sbase + (uint32_t)(buf*32768);
        #pragma unroll
        for (int t = 0; t < 4; t++)
            sts128(off + dstoff[t],
                   f2tf32(av[t].x), f2tf32(av[t].y), f2tf32(av[t].z), f2tf32(av[t].w));
    };
    auto compute = [&](int buf) {
        uint32_t ab = aBase + (uint32_t)(buf*32768);
        uint32_t bb = bBase + (uint32_t)(buf*32768);
        #pragma unroll
        for (int ks = 0; ks < 4; ks++) {
            uint32_t bfr[4][2];
            #pragma unroll
            for (int ntp = 0; ntp < 2; ntp++)
                ldsm4(bb + (uint32_t)(ntp*2048) + bcol[ks],
                      bfr[2*ntp][0], bfr[2*ntp][1], bfr[2*ntp+1][0], bfr[2*ntp+1][1]);
            #pragma unroll
            for (int mt = 0; mt < 4; mt++) {
                uint32_t a0, a1, a2, a3;
                ldsm4(ab + (uint32_t)(mt*2048) + acol[ks], a0, a1, a2, a3);
                #pragma unroll
                for (int nt = 0; nt < 4; nt++)
                    mma_tf32(acc[mt][nt], a0, a1, a2, a3, bfr[nt][0], bfr[nt][1]);
            }
        }
    };

    issueB(0, 0);
    gatherA(0);
    for (int kc = 0; kc < 64; kc++) {
        int buf = kc & 1;
        storeA(buf);
        CP_WAIT0();
        __syncthreads();
        if (kc + 1 < 64) { issueB(kc + 1, buf ^ 1); gatherA(kc + 1); }
        compute(buf);
    }

    int eg = lane >> 2, ec = lane & 3;
    #pragma unroll
    for (int mt = 0; mt < 4; mt++) {
        int r0 = m0 + wm*64 + mt*16 + eg;
        int r1 = r0 + 8;
        #pragma unroll
        for (int nt = 0; nt < 4; nt++) {
            int c0 = wn*32 + nt*8 + 2*ec;
            #pragma unroll
            for (int u = 0; u < 2; u++) {
                int col = c0 + u;
                if (col < LL) {
                    if (r0 < NP) g_part[((size_t)slot*NP + r0)*LL + col] = acc[mt][nt][u];
                    if (r1 < NP) g_part[((size_t)slot*NP + r1)*LL + col] = acc[mt][nt][2+u];
                }
            }
        }
    }
}

// ================= merged weight transposes -> tf32 (flat-index dispatch) =================
// segments: att(4608) path(2304) head(1728) tail(1728) bil(6144) = 16512 blocks
__global__ void ktransAll(const float* __restrict__ Watt, const float* __restrict__ Wpath,
                          const float* __restrict__ Whead, const float* __restrict__ Wtail,
                          const float* __restrict__ Wbil_,
                          uint32_t* __restrict__ oatt, uint32_t* __restrict__ opath,
                          uint32_t* __restrict__ ohead, uint32_t* __restrict__ otail,
                          uint32_t* __restrict__ obil)
{
    __shared__ float t[32][33];
    int id = blockIdx.x;
    const float* in; uint32_t* out; int R, C, Cout, gx;
    if (id < 4608)       { in = Watt;  out = oatt;  R = DIM2; C = DIM4; Cout = DIM4; gx = 96; }
    else if (id < 6912)  { id -= 4608;  in = Wpath; out = opath; R = DIM4; C = DD;  Cout = DD;  gx = 24; }
    else if (id < 8640)  { id -= 6912;  in = Whead; out = ohead; R = DIM3; C = DD;  Cout = DD;  gx = 24; }
    else if (id < 10368) { id -= 8640;  in = Wtail; out = otail; R = DIM3; C = DD;  Cout = DD;  gx = 24; }
    else                 { id -= 10368; in = Wbil_; out = obil;  R = KBIL; C = LL;  Cout = 128; gx = 4;  }
    int c0 = (id % gx)*32, r0 = (id / gx)*32;
    int tx = threadIdx.x, ty = threadIdx.y;
    #pragma unroll
    for (int j = 0; j < 32; j += 8) {
        int r = r0 + ty + j, c = c0 + tx;
        t[ty+j][tx] = (r < R && c < C) ? in[(size_t)r*C + c] : 0.f;
    }
    __syncthreads();
    #pragma unroll
    for (int j = 0; j < 32; j += 8) {
        int c = c0 + ty + j, r = r0 + tx;
        if (c < Cout && r < R) out[(size_t)c*R + r] = f2tf32(t[tx][ty+j]);
    }
}

// batched seq transpose: out[n][d][c] = tf32(seq[n][c][d])
__global__ void ktransB(const float* __restrict__ in, uint32_t* __restrict__ out)
{
    __shared__ float t[32][33];
    int d0 = blockIdx.x*32, c0 = blockIdx.y*32, n = blockIdx.z;
    int tx = threadIdx.x, ty = threadIdx.y;
    const float* inb = in + (size_t)n*CC*DD;
    uint32_t* outb = out + (size_t)n*DD*CC;
    #pragma unroll
    for (int j = 0; j < 32; j += 8)
        t[ty+j][tx] = inb[(size_t)(c0+ty+j)*DD + d0 + tx];
    __syncthreads();
    #pragma unroll
    for (int j = 0; j < 32; j += 8)
        outb[(size_t)(d0+ty+j)*CC + c0 + tx] = f2tf32(t[tx][ty+j]);
}

// ---------------- K1a: per-mention gather (320 blocks) ----------------
__global__ void k_gatherm(const float* __restrict__ seq, const float* __restrict__ att,
                          const int* __restrict__ ms)
{
    int g = blockIdx.x;             // ne*MMENT + m
    int ne = g / MMENT;
    int n  = ne / EE;
    int tid = threadIdx.x;
    int pos = ms[g] + 1;
    const float* srow = seq + ((size_t)n*CC + pos)*DD;
    float* erow = g_eemb + (size_t)g*DD;
    for (int d = tid; d < DD; d += 256) erow[d] = srow[d];
    float* arow = g_eatt + (size_t)g*CC;
    for (int c = tid; c < CC; c += 256) {
        float s = 0.f;
        #pragma unroll
        for (int h = 0; h < HH; h++)
            s += att[(((size_t)n*HH + h)*CC + pos)*CC + c];
        arow[c] = s * (1.0f/HH);
    }
}

// ---------------- K1b: logsumexp over mentions (80 blocks) ----------------
__global__ void k_lse()
{
    int ne = blockIdx.x;
    int tid = threadIdx.x;
    for (int d = tid; d < DD; d += 256) {
        float x0 = g_eemb[((size_t)ne*MMENT+0)*DD+d];
        float x1 = g_eemb[((size_t)ne*MMENT+1)*DD+d];
        float x2 = g_eemb[((size_t)ne*MMENT+2)*DD+d];
        float x3 = g_eemb[((size_t)ne*MMENT+3)*DD+d];
        float mx = fmaxf(fmaxf(x0,x1), fmaxf(x2,x3));
        float s = expf(x0-mx)+expf(x1-mx)+expf(x2-mx)+expf(x3-mx);
        g_glob[(size_t)ne*DD + d] = mx + logf(s);
    }
}

// ---------------- K3: edge ----------------
__global__ void k_edge(const float* __restrict__ bm)
{
    int idx = blockIdx.x*blockDim.x + threadIdx.x;
    const int total = NN*EE*EE*DD;
    if (idx >= total) return;
    int d = idx % DD;
    int v = (idx / DD) % EE;
    int u = (idx / (DD*EE)) % EE;
    int n = idx / (DD*EE*EE);
    float val = g_A[((size_t)n*EE+u)*DD+d] + g_B[((size_t)n*EE+v)*DD+d] + bm[d];
    g_edge[idx] = fmaxf(val, 0.f);
}

// ---------------- K4: pair attention ----------------
__global__ void k_pair(const int* __restrict__ hts, const int* __restrict__ ms)
{
    int r = blockIdx.x;
    int n = r / PP;
    int h = hts[r*2 + 0];
    int t = hts[r*2 + 1];
    __shared__ int   s_ph[MMENT], s_pt[MMENT];
    __shared__ float s_phatt[MMENT], s_ptatt[MMENT];
    __shared__ float s_red[256];
    int tid = threadIdx.x;
    if (tid < MMENT) {
        s_ph[tid] = ms[((size_t)n*EE+h)*MMENT + tid] + 1;
        s_pt[tid] = ms[((size_t)n*EE+t)*MMENT + tid] + 1;
    }
    __syncthreads();
    if (tid < 2*MMENT) {
        int m2 = tid & (MMENT-1);
        float s = 0.f;
        if (tid < MMENT) {
            for (int m1 = 0; m1 < MMENT; m1++)
                s += g_eatt[((size_t)(n*EE+h)*MMENT+m1)*CC + s_pt[m2]];
            s_phatt[m2] = s * (1.f/MMENT);
        } else {
            for (int m1 = 0; m1 < MMENT; m1++)
                s += g_eatt[((size_t)(n*EE+t)*MMENT+m1)*CC + s_ph[m2]];
            s_ptatt[m2] = s * (1.f/MMENT);
        }
    }
    __syncthreads();
    if (tid == 0) {
        float sh = 1e-5f, st = 1e-5f;
        for (int m = 0; m < MMENT; m++) { sh += s_phatt[m]; st += s_ptatt[m]; }
        float ih = 1.f/sh, it = 1.f/st;
        for (int m = 0; m < MMENT; m++) { s_phatt[m] *= ih; s_ptatt[m] *= it; }
    }
    __syncthreads();
    for (int d = tid; d < DD; d += blockDim.x) {
        float nh = 0.f, nt = 0.f;
        #pragma unroll
        for (int m = 0; m < MMENT; m++) {
            nh += s_ptatt[m]*g_eemb[((size_t)(n*EE+h)*MMENT+m)*DD + d];
            nt += s_phatt[m]*g_eemb[((size_t)(n*EE+t)*MMENT+m)*DD + d];
        }
        uint32_t nh32 = f2tf32(nh), nt32 = f2tf32(nt);
        g_hcat32[(size_t)r*DIM3 + d] = nh32;
        g_tcat32[(size_t)r*DIM3 + d] = nt32;
        g_q32[(size_t)r*DIM2 + d]      = nh32;
        g_q32[(size_t)r*DIM2 + DD + d] = nt32;
    }
    float local = 0.f;
    for (int c = tid; c < CC; c += blockDim.x) {
        float na = 0.f, ta = 0.f;
        #pragma unroll
        for (int m = 0; m < MMENT; m++) {
            na += s_ptatt[m]*g_eatt[((size_t)(n*EE+h)*MMENT+m)*CC + c];
            ta += s_phatt[m]*g_eatt[((size_t)(n*EE+t)*MMENT+m)*CC + c];
        }
        float v = na*ta;
        g_pa[(size_t)r*CC + c] = v;
        local += v;
    }
    s_red[tid] = local;
    __syncthreads();
    for (int off = 128; off > 0; off >>= 1) {
        if (tid < off) s_red[tid] += s_red[tid+off];
        __syncthreads();
    }
    float inv = 1.f/(s_red[0] + 1e-5f);
    for (int c = tid; c < CC; c += blockDim.x)
        g_pa32[(size_t)r*CC + c] = f2tf32(g_pa[(size_t)r*CC + c]*inv);
}

// ---------------- fp32 SGEMM (Wm1+Wm2 merged) ----------------
__global__ void __launch_bounds__(256) sgemm(
    int M, int Nn, int Kc, int S,
    const float* __restrict__ A, int lda,
    const float* __restrict__ B, const float* __restrict__ B2, int ldb,
    float* __restrict__ part)
{
    int z = blockIdx.z;
    int s = z % S, b = z / S;
    const float* Ab = A + (size_t)s*Kc;
    const float* Bb = ((b && B2) ? B2 : B) + (size_t)s*Kc*ldb;
    int m0 = blockIdx.y*128, n0 = blockIdx.x*128;
    __shared__ float As[8][128];
    __shared__ float Bs[8][128];
    int tid = threadIdx.x;
    int arow = tid >> 1, ak = (tid & 1)*4;
    int bk = tid >> 5,  bn = (tid & 31)*4;
    int tx = tid & 15,  ty = tid >> 4;
    float acc[8][8];
    #pragma unroll
    for (int i = 0; i < 8; i++)
        #pragma unroll
        for (int j = 0; j < 8; j++) acc[i][j] = 0.f;
    for (int k0 = 0; k0 < Kc; k0 += 8) {
        float4 av = make_float4(0.f,0.f,0.f,0.f);
        if (m0 + arow < M)
            av = *(const float4*)(Ab + (size_t)(m0+arow)*lda + k0 + ak);
        float4 bvv = *(const float4*)(Bb + (size_t)(k0+bk)*ldb + n0 + bn);
        __syncthreads();
        As[ak+0][arow] = av.x; As[ak+1][arow] = av.y;
        As[ak+2][arow] = av.z; As[ak+3][arow] = av.w;
        *(float4*)&Bs[bk][bn] = bvv;
        __syncthreads();
        #pragma unroll
        for (int kk = 0; kk < 8; kk++) {
            float a[8], bb[8];
            *(float4*)(a)    = *(const float4*)&As[kk][ty*8];
            *(float4*)(a+4)  = *(const float4*)&As[kk][ty*8+4];
            *(float4*)(bb)   = *(const float4*)&Bs[kk][tx*8];
            *(float4*)(bb+4) = *(const float4*)&Bs[kk][tx*8+4];
            #pragma unroll
            for (int i = 0; i < 8; i++)
                #pragma unroll
                for (int j = 0; j < 8; j++)
                    acc[i][j] += a[i]*bb[j];
        }
    }
    float* pbase = part + ((size_t)z*M)*Nn;
    #pragma unroll
    for (int i = 0; i < 8; i++) {
        int r = m0 + ty*8 + i;
        if (r < M) {
            float* prow = pbase + (size_t)r*Nn + n0 + tx*8;
            *(float4*)(prow)   = make_float4(acc[i][0],acc[i][1],acc[i][2],acc[i][3]);
            *(float4*)(prow+4) = make_float4(acc[i][4],acc[i][5],acc[i][6],acc[i][7]);
        }
    }
}

// merged Wm reduce
__global__ void k_redwm()
{
    int idx = blockIdx.x*blockDim.x + threadIdx.x;
    const int total = NN*EE*DD;
    if (idx >= total) return;
    float a = 0.f, b = 0.f;
    #pragma unroll
    for (int s = 0; s < 12; s++) {
        a += g_partm[(size_t)s*total + idx];
        b += g_partm[(size_t)(s+12)*total + idx];
    }
    g_A[idx] = a;
    g_B[idx] = b;
}

// path reduce (S=4, tf32 dual)
__global__ void reduce_ep(const float* __restrict__ part, int S, int Mtot, int Nn,
                          const float* __restrict__ bias, int dorelu, int tf32out,
                          float* __restrict__ dst1, int ld1,
                          float* __restrict__ dst2, int ld2)
{
    int idx = blockIdx.x*blockDim.x + threadIdx.x;
    if (idx >= Mtot*Nn) return;
    int r = idx / Nn, c = idx % Nn;
    float v = 0.f;
    for (int s = 0; s < S; s++)
        v += part[((size_t)s*Mtot + r)*Nn + c];
    if (bias) v += bias[c];
    if (dorelu) v = fmaxf(v, 0.f);
    if (tf32out) {
        uint32_t u = f2tf32(v);
        ((uint32_t*)dst1)[(size_t)r*ld1 + c] = u;
        if (dst2) ((uint32_t*)dst2)[(size_t)r*ld2 + c] = u;
    } else {
        dst1[(size_t)r*ld1 + c] = v;
        if (dst2) dst2[(size_t)r*ld2 + c] = v;
    }
}

// merged head/tail reduce: grid.y = 2 (0=head slots 0,1 -> hs; 1=tail slots 2,3 -> ts)
__global__ void reduce_ep2(const float* __restrict__ biasA, const float* __restrict__ biasB)
{
    int b = blockIdx.y;
    int idx = blockIdx.x*blockDim.x + threadIdx.x;
    if (idx >= NP*DD) return;
    int r = idx / DD, c = idx % DD;
    const float* p = g_part + (size_t)(2*b)*NP*DD;
    float v = p[(size_t)r*DD + c] + p[(size_t)NP*DD + (size_t)r*DD + c];
    v += (b ? biasB : biasA)[c];
    v = fmaxf(v, 0.f);
    (b ? g_ts : g_hs)[(size_t)r*DD + c] = v;
}

// ---------------- grouped score ----------------
__global__ void __launch_bounds__(256) k_score(const float* __restrict__ qW)
{
    extern __shared__ float sm[];
    int e = blockIdx.x, kk = blockIdx.y, n = blockIdx.z;
    int tid = threadIdx.x;
    bool strided = (kk == 1) || (kk == 3);
    bool grouph  = (kk == 0) || (kk == 3);
    for (int idx = tid; idx < EE*DD; idx += 256) {
        int v = idx / DD, d = idx % DD;
        size_t off = strided ? (((size_t)(n*EE + v)*EE + e))*DD + d
                             : (((size_t)(n*EE + e)*EE + v))*DD + d;
        sm[idx] = g_edge[off];
    }
    __syncthreads();
    int wid = tid >> 5, lane = tid & 31;
    for (int jj = wid; jj < EE-1; jj += 8) {
        int p = group_pair(n, e, jj, grouph);
        const float* qrow = qW + (size_t)p*DIM4 + kk*DD;
        float q[24];
        #pragma unroll
        for (int u = 0; u < 24; u++) q[u] = qrow[lane + 32*u];
        for (int v = 0; v < EE; v++) {
            const float* smv = sm + v*DD;
            float acc = 0.f;
            #pragma unroll
            for (int u = 0; u < 24; u++) acc += q[u]*smv[lane + 32*u];
            #pragma unroll
            for (int o = 16; o; o >>= 1) acc += __shfl_down_sync(0xffffffffu, acc, o);
            if (lane == 0) g_spart[((size_t)kk*NP + p)*EE + v] = acc;
        }
    }
}

// ---------------- softmax ----------------
__global__ void k_softmax(const int* __restrict__ hts, const float* __restrict__ battp)
{
    int p = blockIdx.x;
    int lane = threadIdx.x;
    int h = hts[p*2], t = hts[p*2+1];
    float s = -1e38f;
    if (lane < EE) {
        s = g_spart[((size_t)0*NP+p)*EE+lane] + g_spart[((size_t)1*NP+p)*EE+lane]
          + g_spart[((size_t)2*NP+p)*EE+lane] + g_spart[((size_t)3*NP+p)*EE+lane]
          + battp[0];
        if (lane == h || lane == t) s = NEGV;
    }
    float mx = s;
    #pragma unroll
    for (int o = 16; o; o >>= 1) mx = fmaxf(mx, __shfl_xor_sync(0xffffffffu, mx, o));
    float ex = (lane < EE) ? expf(s - mx) : 0.f;
    float sum = ex;
    #pragma unroll
    for (int o = 16; o; o >>= 1) sum += __shfl_xor_sync(0xffffffffu, sum, o);
    if (lane < EE) g_aw[(size_t)p*EE + lane] = ex/sum;
}

// ---------------- grouped path ----------------
__global__ void __launch_bounds__(256) k_pathg()
{
    extern __shared__ float sm[];
    float* aws = sm + EE*DD;
    int e = blockIdx.x, kk = blockIdx.y, n = blockIdx.z;
    int tid = threadIdx.x;
    bool strided = (kk == 1) || (kk == 3);
    bool grouph  = (kk == 0) || (kk == 3);
    for (int idx = tid; idx < EE*DD; idx += 256) {
        int v = idx / DD, d = idx % DD;
        size_t off = strided ? (((size_t)(n*EE + v)*EE + e))*DD + d
                             : (((size_t)(n*EE + e)*EE + v))*DD + d;
        sm[idx] = g_edge[off];
    }
    for (int idx = tid; idx < 19*EE; idx += 256) {
        int jj = idx / EE, v = idx % EE;
        int p = group_pair(n, e, jj, grouph);
        aws[idx] = g_aw[(size_t)p*EE + v];
    }
    __syncthreads();
    for (int idx = tid; idx < 19*DD; idx += 256) {
        int jj = idx / DD, d = idx % DD;
        float acc = 0.f;
        #pragma unroll
        for (int v = 0; v < EE; v++)
            acc += aws[jj*EE + v]*sm[v*DD + d];
        int p = group_pair(n, e, jj, grouph);
        g_praw32[(size_t)p*DIM4 + kk*DD + d] = f2tf32(acc);
    }
}

__global__ void k_bilred(const float* __restrict__ bbil, float* __restrict__ out)
{
    int idx = blockIdx.x*blockDim.x + threadIdx.x;
    if (idx >= NP*LL) return;
    int r = idx / LL, l = idx % LL;
    float v = bbil[l];
    #pragma unroll
    for (int k = 0; k < 24; k++)
        v += g_part[((size_t)k*NP + r)*LL + l];
    out[idx] = v;
}

// ---------------- launcher ----------------
static void* symaddr(const void* sym)
{
    void* p = nullptr;
    cudaGetSymbolAddress(&p, sym);
    return p;
}

extern "C" void kernel_launch(void* const* d_in, const int* in_sizes, int n_in,
                              void* d_out, int out_size)
{
    const float* seq   = (const float*)d_in[0];
    const float* att   = (const float*)d_in[1];
    const int*   ms    = (const int*)  d_in[2];
    const int*   hts   = (const int*)  d_in[3];
    const float* Wm1   = (const float*)d_in[4];
    const float* Wm2   = (const float*)d_in[5];
    const float* bm    = (const float*)d_in[6];
    const float* Watt  = (const float*)d_in[7];
    const float* batt  = (const float*)d_in[8];
    const float* Wpath = (const float*)d_in[9];
    const float* bpath = (const float*)d_in[10];
    const float* Whead = (const float*)d_in[11];
    const float* bhead = (const float*)d_in[12];
    const float* Wtail = (const float*)d_in[13];
    const float* btail = (const float*)d_in[14];
    const float* Wbil  = (const float*)d_in[15];
    const float* bbil  = (const float*)d_in[16];
    float* out = (float*)d_out;

    float*    glob   = (float*)symaddr(g_glob);
    float*    qW     = (float*)symaddr(g_qW);
    float*    part   = (float*)symaddr(g_part);
    float*    partm  = (float*)symaddr(g_partm);
    uint32_t* pa32   = (uint32_t*)symaddr(g_pa32);
    uint32_t* seqT32 = (uint32_t*)symaddr(g_seqT32);
    uint32_t* q32    = (uint32_t*)symaddr(g_q32);
    uint32_t* hcat32 = (uint32_t*)symaddr(g_hcat32);
    uint32_t* tcat32 = (uint32_t*)symaddr(g_tcat32);
    uint32_t* praw32 = (uint32_t*)symaddr(g_praw32);
    uint32_t* wTatt  = (uint32_t*)symaddr(g_wT_att32);
    uint32_t* wTpath = (uint32_t*)symaddr(g_wT_path32);
    uint32_t* wThead = (uint32_t*)symaddr(g_wT_head32);
    uint32_t* wTtail = (uint32_t*)symaddr(g_wT_tail32);
    uint32_t* wTbil  = (uint32_t*)symaddr(g_wT_bil32);

    const int SMEM_WG = 98304;
    const int SMEM_WB = 98304;
    const int SMEM_SC = EE*DD*4;
    const int SMEM_PG = EE*DD*4 + 19*EE*4;
    cudaFuncSetAttribute(wgemm,  cudaFuncAttributeMaxDynamicSharedMemorySize, SMEM_WG);
    cudaFuncSetAttribute(wbil,   cudaFuncAttributeMaxDynamicSharedMemorySize, SMEM_WB);
    cudaFuncSetAttribute(k_score, cudaFuncAttributeMaxDynamicSharedMemorySize, SMEM_SC);
    cudaFuncSetAttribute(k_pathg, cudaFuncAttributeMaxDynamicSharedMemorySize, SMEM_PG);

    // --- ordered so launch index 3 (ncu capture slot) is the qW wgemm ---
    k_gatherm<<<NN*EE*MMENT, 256>>>(seq, att, ms);                                 // 0
    k_pair<<<NP, 256>>>(hts, ms);                                                  // 1
    ktransAll<<<16512, dim3(32,8)>>>(Watt, Wpath, Whead, Wtail, Wbil,
                                     wTatt, wTpath, wThead, wTtail, wTbil);        // 2
    // 3: qW = q @ Watt (tf32 mma) <-- ncu profiles this
    wgemm<<<dim3(24,12,1), 256, SMEM_WG>>>(NP, 48, 1,
        q32, DIM2, 0, wTatt, DIM2, 0, nullptr, nullptr,
        qW, DIM4, 0, nullptr, nullptr, 0, 0,
        nullptr, nullptr, 0, 0, nullptr, 0, 0);

    // logsumexp (only feeds Wm sgemm)
    k_lse<<<NN*EE, 256>>>();

    // Wm1+Wm2 merged (fp32, split-K 12 each) -> merged reduce -> edge
    sgemm<<<dim3(6,1,24), 256>>>(NN*EE, DD, 64, 12, glob, DD, Wm1, Wm2, DD, partm);
    k_redwm<<<(NN*EE*DD+255)/256, 256>>>();
    k_edge<<<(NN*EE*EE*DD+255)/256, 256>>>(bm);

    // rs = pa @ seq (tf32 mma, per-doc batch, direct dual tf32 epilogue)
    ktransB<<<dim3(DD/32, CC/32, NN), dim3(32,8)>>>(seq, seqT32);
    wgemm<<<dim3(6,3,NN), 256, SMEM_WG>>>(PP, 16, 1,
        pa32, CC, (long long)PP*CC, seqT32, CC, (long long)DD*CC, nullptr, nullptr,
        (float*)(hcat32 + DD), DIM3, (long long)PP*DIM3, nullptr,
        (float*)(tcat32 + DD), DIM3, (long long)PP*DIM3,
        nullptr, nullptr, 0, 1, nullptr, 0, 0);

    // grouped score -> softmax -> grouped path
    k_score<<<dim3(EE,4,NN), 256, SMEM_SC>>>(qW);
    k_softmax<<<NP, 32>>>(hts, batt);
    k_pathg<<<dim3(EE,4,NN), 256, SMEM_PG>>>();

    // path = relu(pathraw @ Wpath + bpath): Sr=4 -> 288 CTAs
    wgemm<<<dim3(6,12,4), 256, SMEM_WG>>>(NP, 24, 4,
        praw32, DIM4, 0, wTpath, DIM4, 0, nullptr, nullptr,
        nullptr, 0, 0, nullptr, nullptr, 0, 0,
        nullptr, nullptr, 0, 0, part, NP, DD);
    reduce_ep<<<(NP*DD+255)/256, 256>>>(part, 4, NP, DD, bpath, 1, 1,
                                        (float*)(hcat32 + 2*DD), DIM3,
                                        (float*)(tcat32 + 2*DD), DIM3);

    // hs / ts projections: merged batch + Sr=2 partials -> 288 CTAs, merged reduce
    wgemm<<<dim3(6,12,4), 256, SMEM_WG>>>(NP, 36, 2,
        hcat32, DIM3, 0, wThead, DIM3, 0, tcat32, wTtail,
        nullptr, 0, 0, nullptr, nullptr, 0, 0,
        nullptr, nullptr, 0, 0, part, NP, DD);
    reduce_ep2<<<dim3((NP*DD+255)/256, 2), 256>>>(bhead, btail);

    // bilinear head: grid (12, 24), partial slots 0..23
    wbil<<<dim3(12,24), 256, SMEM_WB>>>(wTbil);
    k_bilred<<<(NP*LL+255)/256, 256>>>(bbil, out);
}

// round 17
// speedup vs baseline: 1.0814x; 1.0396x over previous
#include <cuda_runtime.h>
#include <cstdint>
#include <math.h>

#define NN 4
#define CC 512
#define DD 768
#define HH 12
#define EE 20
#define MMENT 4
#define PP 380
#define NP 1520
#define LL 97
#define DIM2 1536
#define DIM3 2304
#define DIM4 3072
#define KBIL 49152
#define NEGV (-1e30f)

// ---------------- static device scratch ----------------
__device__ float g_eemb[NN*EE*MMENT*DD];
__device__ float g_eatt[NN*EE*MMENT*CC];
__device__ float g_glob[NN*EE*DD];
__device__ float g_A[NN*EE*DD];
__device__ float g_B[NN*EE*DD];
__device__ float g_edge[NN*EE*EE*DD];
__device__ float g_pa[NP*CC];
__device__ float g_qW[NP*DIM4];
__device__ float g_hs[NP*DD];
__device__ float g_ts[NP*DD];
__device__ float g_part[4*NP*DD];
__device__ float g_partm[24*NN*EE*DD];
__device__ float g_spart[4*NP*EE];
__device__ float g_aw[NP*EE];
// tf32 (u32 bit pattern) GEMM operands
__device__ uint32_t g_pa32[NP*CC];
__device__ uint32_t g_seqT32[NN*DD*CC];
__device__ uint32_t g_q32[NP*DIM2];
__device__ uint32_t g_hcat32[NP*DIM3];
__device__ uint32_t g_tcat32[NP*DIM3];
__device__ uint32_t g_praw32[NP*DIM4];
__device__ uint32_t g_wT_att32[DIM4*DIM2];
__device__ uint32_t g_wT_path32[DD*DIM4];
__device__ uint32_t g_wT_head32[DD*DIM3];
__device__ uint32_t g_wT_tail32[DD*DIM3];
__device__ uint32_t g_wT_bil32[128*KBIL];   // rows 97..127 zero

// ---------------- helpers ----------------
__device__ __forceinline__ uint32_t f2tf32(float f) {
    uint32_t r;
    asm("cvt.rna.tf32.f32 %0, %1;" : "=r"(r) : "f"(f));
    return r;
}
__device__ __forceinline__ void mma_tf32(float* d, uint32_t a0, uint32_t a1,
                                         uint32_t a2, uint32_t a3,
                                         uint32_t b0, uint32_t b1)
{
    asm volatile(
        "mma.sync.aligned.m16n8k8.row.col.f32.tf32.tf32.f32 "
        "{%0,%1,%2,%3}, {%4,%5,%6,%7}, {%8,%9}, {%0,%1,%2,%3};"
        : "+f"(d[0]), "+f"(d[1]), "+f"(d[2]), "+f"(d[3])
        : "r"(a0), "r"(a1), "r"(a2), "r"(a3), "r"(b0), "r"(b1));
}
__device__ __forceinline__ void ldsm4(uint32_t addr, uint32_t& a, uint32_t& b,
                                      uint32_t& c, uint32_t& d)
{
    asm volatile("ldmatrix.sync.aligned.m8n8.x4.shared.b16 {%0,%1,%2,%3}, [%4];"
                 : "=r"(a), "=r"(b), "=r"(c), "=r"(d) : "r"(addr));
}
__device__ __forceinline__ void sts128(uint32_t addr, uint32_t x, uint32_t y,
                                       uint32_t z, uint32_t w)
{
    asm volatile("st.shared.v4.b32 [%0], {%1,%2,%3,%4};"
                 :: "r"(addr), "r"(x), "r"(y), "r"(z), "r"(w) : "memory");
}
__device__ __forceinline__ void cpa16(uint32_t dst, const void* src, uint32_t sz)
{
    asm volatile("cp.async.cg.shared.global [%0], [%1], 16, %2;"
                 :: "r"(dst), "l"(src), "r"(sz) : "memory");
}
#define CP_COMMIT() asm volatile("cp.async.commit_group;" ::: "memory")
#define CP_WAIT0()  asm volatile("cp.async.wait_group 0;" ::: "memory")
#define CP_WAIT1()  asm volatile("cp.async.wait_group 1;" ::: "memory")

// pair-index helper
__device__ __forceinline__ int group_pair(int n, int e, int jj, bool grouph)
{
    if (grouph) return n*PP + e*19 + jj;
    int i = jj + (jj >= e);
    return n*PP + i*19 + (e < i ? e : e - 1);
}

// ================ tf32 warp-mma GEMM: 3-stage cp.async pipeline + ldmatrix ================
__global__ void __launch_bounds__(256,2) wgemm(
    int M, int nchunks, int Sr,
    const uint32_t* __restrict__ A, int lda, long long sAb,
    const uint32_t* __restrict__ BT, int ldbt, long long sBTb,
    const uint32_t* __restrict__ A2, const uint32_t* __restrict__ BT2,
    float* __restrict__ dst1, int ld1, long long d1b, float* __restrict__ dst1b,
    float* __restrict__ dst2, int ld2, long long d2b,
    const float* __restrict__ bias, const float* __restrict__ bias2,
    int relu, int tf32out,
    float* __restrict__ part, int Mtot, int Nn)
{
    extern __shared__ float smf[];
    uint32_t sbase = (uint32_t)__cvta_generic_to_shared(smf);
    int tid = threadIdx.x;
    int lane = tid & 31, wid = tid >> 5;
    int wm = wid >> 2, wn = wid & 3;
    int m0 = blockIdx.y*128, n0 = blockIdx.x*128;
    int z = blockIdx.z;
    int s = z % Sr, b = z / Sr;
    const uint32_t* Ause;
    const uint32_t* BTuse;
    float* d1; float* d2;
    const float* biasu;
    if (A2) {
        Ause  = b ? A2  : A;
        BTuse = b ? BT2 : BT;
        d1 = b ? dst1b : dst1;
        d2 = dst2;
        biasu = (b && bias2) ? bias2 : bias;
    } else {
        Ause  = A + (size_t)b*sAb;
        BTuse = BT + (size_t)b*sBTb;
        d1 = dst1 ? dst1 + (size_t)b*d1b : nullptr;
        d2 = dst2 ? dst2 + (size_t)b*d2b : nullptr;
        biasu = bias;
    }
    int kbase = s*nchunks*32;

    int r0g = tid >> 3;
    int qf  = tid & 7;
    uint32_t dstoff[4];
    const uint32_t* aS[4]; uint32_t aSz[4];
    const uint32_t* bS[4];
    #pragma unroll
    for (int t = 0; t < 4; t++) {
        int r = r0g + t*32;
        dstoff[t] = (uint32_t)(r*128) + (uint32_t)((qf ^ (r & 7)) << 4);
        int rm = m0 + r;
        int rcl = rm < M ? rm : (M-1);
        aS[t]  = Ause + (size_t)rcl*lda + kbase + qf*4;
        aSz[t] = (rm < M) ? 16u : 0u;
        bS[t]  = BTuse + (size_t)(n0 + r)*ldbt + kbase + qf*4;
    }

    int lg = lane >> 3, l7 = lane & 7;
    int arow = wm*64 + ((lg & 1) << 3) + l7;
    int brow = wn*32 + ((lg >> 1) << 3) + l7;
    uint32_t acol[4], bcol[4];
    #pragma unroll
    for (int ks = 0; ks < 4; ks++) {
        acol[ks] = (uint32_t)(((((ks<<1) + (lg>>1)) ^ (arow & 7))) << 4);
        bcol[ks] = (uint32_t)(((((ks<<1) + (lg&1))  ^ (brow & 7))) << 4);
    }
    uint32_t aBase = sbase + (uint32_t)(arow*128);
    uint32_t bBase = sbase + 16384u + (uint32_t)(brow*128);

    float acc[4][4][4];
    #pragma unroll
    for (int i = 0; i < 4; i++)
        #pragma unroll
        for (int j = 0; j < 4; j++)
            #pragma unroll
            for (int k = 0; k < 4; k++) acc[i][j][k] = 0.f;

    auto issue = [&](int kc, int st) {
        uint32_t off = sbase + (uint32_t)(st*32768);
        int ko = kc*32;
        #pragma unroll
        for (int t = 0; t < 4; t++) {
            cpa16(off + dstoff[t], aS[t] + ko, aSz[t]);
            cpa16(off + 16384u + dstoff[t], bS[t] + ko, 16u);
        }
        CP_COMMIT();
    };
    auto compute = [&](int st) {
        uint32_t ab = aBase + (uint32_t)(st*32768);
        uint32_t bb = bBase + (uint32_t)(st*32768);
        #pragma unroll
        for (int ks = 0; ks < 4; ks++) {
            uint32_t bfr[4][2];
            #pragma unroll
            for (int ntp = 0; ntp < 2; ntp++)
                ldsm4(bb + (uint32_t)(ntp*2048) + bcol[ks],
                      bfr[2*ntp][0], bfr[2*ntp][1], bfr[2*ntp+1][0], bfr[2*ntp+1][1]);
            #pragma unroll
            for (int mt = 0; mt < 4; mt++) {
                uint32_t a0, a1, a2, a3;
                ldsm4(ab + (uint32_t)(mt*2048) + acol[ks], a0, a1, a2, a3);
                #pragma unroll
                for (int nt = 0; nt < 4; nt++)
                    mma_tf32(acc[mt][nt], a0, a1, a2, a3, bfr[nt][0], bfr[nt][1]);
            }
        }
    };

    issue(0, 0);
    if (nchunks > 1) issue(1, 1);
    int st = 0;
    for (int kc = 0; kc < nchunks; kc++) {
        if (kc + 1 < nchunks) CP_WAIT1(); else CP_WAIT0();
        __syncthreads();
        if (kc + 2 < nchunks) {
            int st2 = st + 2; if (st2 >= 3) st2 -= 3;
            issue(kc + 2, st2);
        }
        compute(st);
        st = (st == 2) ? 0 : st + 1;
    }

    int eg = lane >> 2, ec = lane & 3;
    #pragma unroll
    for (int mt = 0; mt < 4; mt++) {
        int r0 = m0 + wm*64 + mt*16 + eg;
        int r1 = r0 + 8;
        #pragma unroll
        for (int nt = 0; nt < 4; nt++) {
            int c0 = n0 + wn*32 + nt*8 + 2*ec;
            if (part) {
                float* p0 = part + ((size_t)z*Mtot + r0)*Nn + c0;
                float* p1 = part + ((size_t)z*Mtot + r1)*Nn + c0;
                if (r0 < M) { p0[0] = acc[mt][nt][0]; p0[1] = acc[mt][nt][1]; }
                if (r1 < M) { p1[0] = acc[mt][nt][2]; p1[1] = acc[mt][nt][3]; }
            } else {
                float b0 = biasu ? biasu[c0] : 0.f;
                float b1 = biasu ? biasu[c0+1] : 0.f;
                float v0 = acc[mt][nt][0] + b0, v1 = acc[mt][nt][1] + b1;
                float v2 = acc[mt][nt][2] + b0, v3 = acc[mt][nt][3] + b1;
                if (relu) { v0=fmaxf(v0,0.f); v1=fmaxf(v1,0.f); v2=fmaxf(v2,0.f); v3=fmaxf(v3,0.f); }
                if (tf32out) {
                    uint32_t u0 = f2tf32(v0), u1 = f2tf32(v1), u2 = f2tf32(v2), u3 = f2tf32(v3);
                    if (r0 < M) {
                        ((uint32_t*)d1)[(size_t)r0*ld1 + c0] = u0;
                        ((uint32_t*)d1)[(size_t)r0*ld1 + c0+1] = u1;
                        if (d2) { ((uint32_t*)d2)[(size_t)r0*ld2 + c0] = u0;
                                  ((uint32_t*)d2)[(size_t)r0*ld2 + c0+1] = u1; }
                    }
                    if (r1 < M) {
                        ((uint32_t*)d1)[(size_t)r1*ld1 + c0] = u2;
                        ((uint32_t*)d1)[(size_t)r1*ld1 + c0+1] = u3;
                        if (d2) { ((uint32_t*)d2)[(size_t)r1*ld2 + c0] = u2;
                                  ((uint32_t*)d2)[(size_t)r1*ld2 + c0+1] = u3; }
                    }
                } else {
                    if (r0 < M) {
                        d1[(size_t)r0*ld1 + c0] = v0; d1[(size_t)r0*ld1 + c0+1] = v1;
                        if (d2) { d2[(size_t)r0*ld2 + c0] = v0; d2[(size_t)r0*ld2 + c0+1] = v1; }
                    }
                    if (r1 < M) {
                        d1[(size_t)r1*ld1 + c0] = v2; d1[(size_t)r1*ld1 + c0+1] = v3;
                        if (d2) { d2[(size_t)r1*ld2 + c0] = v2; d2[(size_t)r1*ld2 + c0+1] = v3; }
                    }
                }
            }
        }
    }
}

// ===== bilinear: grid (12 m-tiles, 24 slots). slot = kb*2 + half; 64 chunks each. =====
__global__ void __launch_bounds__(256,2) wbil(const uint32_t* __restrict__ BT)
{
    extern __shared__ float smf[];
    uint32_t sbase = (uint32_t)__cvta_generic_to_shared(smf);
    float* ts_s = smf + 16384;           // [128][64]
    int tid = threadIdx.x;
    int lane = tid & 31, wid = tid >> 5;
    int wm = wid >> 2, wn = wid & 3;
    int m0 = blockIdx.x*128;
    int slot = blockIdx.y;
    int kb = slot >> 1, half = slot & 1;

    #pragma unroll
    for (int t = 0; t < 8; t++) {
        int idx = tid + t*256;
        int r = idx >> 4, qi = idx & 15;
        int rg = m0 + r;
        float4 v = make_float4(0.f,0.f,0.f,0.f);
        if (rg < NP)
            v = *(const float4*)(g_ts + (size_t)rg*DD + kb*64 + qi*4);
        *(float4*)(ts_s + r*64 + qi*4) = v;
    }
    __syncthreads();

    int r0g = tid >> 3;
    int qf  = tid & 7;
    uint32_t dstoff[4];
    const uint32_t* bS[4];
    int hrow[4]; int hvalid[4];
    #pragma unroll
    for (int t = 0; t < 4; t++) {
        int r = r0g + t*32;
        dstoff[t] = (uint32_t)(r*128) + (uint32_t)((qf ^ (r & 7)) << 4);
        bS[t] = BT + (size_t)r*KBIL + kb*4096 + half*2048 + qf*4;
        hrow[t] = m0 + r;
        hvalid[t] = (m0 + r) < NP;
    }
    int icol0 = kb*64 + half*32;

    int lg = lane >> 3, l7 = lane & 7;
    int arow = wm*64 + ((lg & 1) << 3) + l7;
    int brow = wn*32 + ((lg >> 1) << 3) + l7;
    uint32_t acol[4], bcol[4];
    #pragma unroll
    for (int ks = 0; ks < 4; ks++) {
        acol[ks] = (uint32_t)(((((ks<<1) + (lg>>1)) ^ (arow & 7))) << 4);
        bcol[ks] = (uint32_t)(((((ks<<1) + (lg&1))  ^ (brow & 7))) << 4);
    }
    uint32_t aBase = sbase + (uint32_t)(arow*128);
    uint32_t bBase = sbase + 16384u + (uint32_t)(brow*128);

    float acc[4][4][4];
    #pragma unroll
    for (int i = 0; i < 4; i++)
        #pragma unroll
        for (int j = 0; j < 4; j++)
            #pragma unroll
            for (int k = 0; k < 4; k++) acc[i][j][k] = 0.f;

    float hv[4];
    float4 av[4];
    auto issueB = [&](int kc, int buf) {
        uint32_t off = sbase + (uint32_t)(buf*32768) + 16384u;
        int ko = kc*32;
        #pragma unroll
        for (int t = 0; t < 4; t++)
            cpa16(off + dstoff[t], bS[t] + ko, 16u);
        CP_COMMIT();
    };
    auto gatherA = [&](int kc) {
        if ((kc & 1) == 0) {
            int icol = icol0 + (kc >> 1);
            #pragma unroll
            for (int t = 0; t < 4; t++)
                hv[t] = hvalid[t] ? g_hs[(size_t)hrow[t]*DD + icol] : 0.f;
        }
        int j0 = ((kc & 1) << 5) + qf*4;
        #pragma unroll
        for (int t = 0; t < 4; t++) {
            int r = r0g + t*32;
            float4 tv = *(const float4*)(ts_s + r*64 + j0);
            av[t] = make_float4(hv[t]*tv.x, hv[t]*tv.y, hv[t]*tv.z, hv[t]*tv.w);
        }
    };
    auto storeA = [&](int buf) {
        uint32_t off = sbase + (uint32_t)(buf*32768);
        #pragma unroll
        for (int t = 0; t < 4; t++)
            sts128(off + dstoff[t],
                   f2tf32(av[t].x), f2tf32(av[t].y), f2tf32(av[t].z), f2tf32(av[t].w));
    };
    auto compute = [&](int buf) {
        uint32_t ab = aBase + (uint32_t)(buf*32768);
        uint32_t bb = bBase + (uint32_t)(buf*32768);
        #pragma unroll
        for (int ks = 0; ks < 4; ks++) {
            uint32_t bfr[4][2];
            #pragma unroll
            for (int ntp = 0; ntp < 2; ntp++)
                ldsm4(bb + (uint32_t)(ntp*2048) + bcol[ks],
                      bfr[2*ntp][0], bfr[2*ntp][1], bfr[2*ntp+1][0], bfr[2*ntp+1][1]);
            #pragma unroll
            for (int mt = 0; mt < 4; mt++) {
                uint32_t a0, a1, a2, a3;
                ldsm4(ab + (uint32_t)(mt*2048) + acol[ks], a0, a1, a2, a3);
                #pragma unroll
                for (int nt = 0; nt < 4; nt++)
                    mma_tf32(acc[mt][nt], a0, a1, a2, a3, bfr[nt][0], bfr[nt][1]);
            }
        }
    };

    issueB(0, 0);
    gatherA(0);
    for (int kc = 0; kc < 64; kc++) {
        int buf = kc & 1;
        storeA(buf);
        CP_WAIT0();
        __syncthreads();
        if (kc + 1 < 64) { issueB(kc + 1, buf ^ 1); gatherA(kc + 1); }
        compute(buf);
    }

    int eg = lane >> 2, ec = lane & 3;
    #pragma unroll
    for (int mt = 0; mt < 4; mt++) {
        int r0 = m0 + wm*64 + mt*16 + eg;
        int r1 = r0 + 8;
        #pragma unroll
        for (int nt = 0; nt < 4; nt++) {
            int c0 = wn*32 + nt*8 + 2*ec;
            #pragma unroll
            for (int u = 0; u < 2; u++) {
                int col = c0 + u;
                if (col < LL) {
                    if (r0 < NP) g_part[((size_t)slot*NP + r0)*LL + col] = acc[mt][nt][u];
                    if (r1 < NP) g_part[((size_t)slot*NP + r1)*LL + col] = acc[mt][nt][2+u];
                }
            }
        }
    }
}

// ================= merged weight transposes -> tf32 (flat-index dispatch) =================
__global__ void ktransAll(const float* __restrict__ Watt, const float* __restrict__ Wpath,
                          const float* __restrict__ Whead, const float* __restrict__ Wtail,
                          const float* __restrict__ Wbil_,
                          uint32_t* __restrict__ oatt, uint32_t* __restrict__ opath,
                          uint32_t* __restrict__ ohead, uint32_t* __restrict__ otail,
                          uint32_t* __restrict__ obil)
{
    __shared__ float t[32][33];
    int id = blockIdx.x;
    const float* in; uint32_t* out; int R, C, Cout, gx;
    if (id < 4608)       { in = Watt;  out = oatt;  R = DIM2; C = DIM4; Cout = DIM4; gx = 96; }
    else if (id < 6912)  { id -= 4608;  in = Wpath; out = opath; R = DIM4; C = DD;  Cout = DD;  gx = 24; }
    else if (id < 8640)  { id -= 6912;  in = Whead; out = ohead; R = DIM3; C = DD;  Cout = DD;  gx = 24; }
    else if (id < 10368) { id -= 8640;  in = Wtail; out = otail; R = DIM3; C = DD;  Cout = DD;  gx = 24; }
    else                 { id -= 10368; in = Wbil_; out = obil;  R = KBIL; C = LL;  Cout = 128; gx = 4;  }
    int c0 = (id % gx)*32, r0 = (id / gx)*32;
    int tx = threadIdx.x, ty = threadIdx.y;
    #pragma unroll
    for (int j = 0; j < 32; j += 8) {
        int r = r0 + ty + j, c = c0 + tx;
        t[ty+j][tx] = (r < R && c < C) ? in[(size_t)r*C + c] : 0.f;
    }
    __syncthreads();
    #pragma unroll
    for (int j = 0; j < 32; j += 8) {
        int c = c0 + ty + j, r = r0 + tx;
        if (c < Cout && r < R) out[(size_t)c*R + r] = f2tf32(t[tx][ty+j]);
    }
}

// batched seq transpose: out[n][d][c] = tf32(seq[n][c][d])
__global__ void ktransB(const float* __restrict__ in, uint32_t* __restrict__ out)
{
    __shared__ float t[32][33];
    int d0 = blockIdx.x*32, c0 = blockIdx.y*32, n = blockIdx.z;
    int tx = threadIdx.x, ty = threadIdx.y;
    const float* inb = in + (size_t)n*CC*DD;
    uint32_t* outb = out + (size_t)n*DD*CC;
    #pragma unroll
    for (int j = 0; j < 32; j += 8)
        t[ty+j][tx] = inb[(size_t)(c0+ty+j)*DD + d0 + tx];
    __syncthreads();
    #pragma unroll
    for (int j = 0; j < 32; j += 8)
        outb[(size_t)(d0+ty+j)*CC + c0 + tx] = f2tf32(t[tx][ty+j]);
}

// ---------------- K1a: per-mention gather ----------------
__global__ void k_gatherm(const float* __restrict__ seq, const float* __restrict__ att,
                          const int* __restrict__ ms)
{
    int g = blockIdx.x;
    int ne = g / MMENT;
    int n  = ne / EE;
    int tid = threadIdx.x;
    int pos = ms[g] + 1;
    const float* srow = seq + ((size_t)n*CC + pos)*DD;
    float* erow = g_eemb + (size_t)g*DD;
    for (int d = tid; d < DD; d += 256) erow[d] = srow[d];
    float* arow = g_eatt + (size_t)g*CC;
    for (int c = tid; c < CC; c += 256) {
        float s = 0.f;
        #pragma unroll
        for (int h = 0; h < HH; h++)
            s += att[(((size_t)n*HH + h)*CC + pos)*CC + c];
        arow[c] = s * (1.0f/HH);
    }
}

// ---------------- K1b: logsumexp over mentions ----------------
__global__ void k_lse()
{
    int ne = blockIdx.x;
    int tid = threadIdx.x;
    for (int d = tid; d < DD; d += 256) {
        float x0 = g_eemb[((size_t)ne*MMENT+0)*DD+d];
        float x1 = g_eemb[((size_t)ne*MMENT+1)*DD+d];
        float x2 = g_eemb[((size_t)ne*MMENT+2)*DD+d];
        float x3 = g_eemb[((size_t)ne*MMENT+3)*DD+d];
        float mx = fmaxf(fmaxf(x0,x1), fmaxf(x2,x3));
        float s = expf(x0-mx)+expf(x1-mx)+expf(x2-mx)+expf(x3-mx);
        g_glob[(size_t)ne*DD + d] = mx + logf(s);
    }
}

// ---------------- K3: edge ----------------
__global__ void k_edge(const float* __restrict__ bm)
{
    int idx = blockIdx.x*blockDim.x + threadIdx.x;
    const int total = NN*EE*EE*DD;
    if (idx >= total) return;
    int d = idx % DD;
    int v = (idx / DD) % EE;
    int u = (idx / (DD*EE)) % EE;
    int n = idx / (DD*EE*EE);
    float val = g_A[((size_t)n*EE+u)*DD+d] + g_B[((size_t)n*EE+v)*DD+d] + bm[d];
    g_edge[idx] = fmaxf(val, 0.f);
}

// ---------------- K4: pair attention ----------------
__global__ void k_pair(const int* __restrict__ hts, const int* __restrict__ ms)
{
    int r = blockIdx.x;
    int n = r / PP;
    int h = hts[r*2 + 0];
    int t = hts[r*2 + 1];
    __shared__ int   s_ph[MMENT], s_pt[MMENT];
    __shared__ float s_phatt[MMENT], s_ptatt[MMENT];
    __shared__ float s_red[256];
    int tid = threadIdx.x;
    if (tid < MMENT) {
        s_ph[tid] = ms[((size_t)n*EE+h)*MMENT + tid] + 1;
        s_pt[tid] = ms[((size_t)n*EE+t)*MMENT + tid] + 1;
    }
    __syncthreads();
    if (tid < 2*MMENT) {
        int m2 = tid & (MMENT-1);
        float s = 0.f;
        if (tid < MMENT) {
            for (int m1 = 0; m1 < MMENT; m1++)
                s += g_eatt[((size_t)(n*EE+h)*MMENT+m1)*CC + s_pt[m2]];
            s_phatt[m2] = s * (1.f/MMENT);
        } else {
            for (int m1 = 0; m1 < MMENT; m1++)
                s += g_eatt[((size_t)(n*EE+t)*MMENT+m1)*CC + s_ph[m2]];
            s_ptatt[m2] = s * (1.f/MMENT);
        }
    }
    __syncthreads();
    if (tid == 0) {
        float sh = 1e-5f, st = 1e-5f;
        for (int m = 0; m < MMENT; m++) { sh += s_phatt[m]; st += s_ptatt[m]; }
        float ih = 1.f/sh, it = 1.f/st;
        for (int m = 0; m < MMENT; m++) { s_phatt[m] *= ih; s_ptatt[m] *= it; }
    }
    __syncthreads();
    for (int d = tid; d < DD; d += blockDim.x) {
        float nh = 0.f, nt = 0.f;
        #pragma unroll
        for (int m = 0; m < MMENT; m++) {
            nh += s_ptatt[m]*g_eemb[((size_t)(n*EE+h)*MMENT+m)*DD + d];
            nt += s_phatt[m]*g_eemb[((size_t)(n*EE+t)*MMENT+m)*DD + d];
        }
        uint32_t nh32 = f2tf32(nh), nt32 = f2tf32(nt);
        g_hcat32[(size_t)r*DIM3 + d] = nh32;
        g_tcat32[(size_t)r*DIM3 + d] = nt32;
        g_q32[(size_t)r*DIM2 + d]      = nh32;
        g_q32[(size_t)r*DIM2 + DD + d] = nt32;
    }
    float local = 0.f;
    for (int c = tid; c < CC; c += blockDim.x) {
        float na = 0.f, ta = 0.f;
        #pragma unroll
        for (int m = 0; m < MMENT; m++) {
            na += s_ptatt[m]*g_eatt[((size_t)(n*EE+h)*MMENT+m)*CC + c];
            ta += s_phatt[m]*g_eatt[((size_t)(n*EE+t)*MMENT+m)*CC + c];
        }
        float v = na*ta;
        g_pa[(size_t)r*CC + c] = v;
        local += v;
    }
    s_red[tid] = local;
    __syncthreads();
    for (int off = 128; off > 0; off >>= 1) {
        if (tid < off) s_red[tid] += s_red[tid+off];
        __syncthreads();
    }
    float inv = 1.f/(s_red[0] + 1e-5f);
    for (int c = tid; c < CC; c += blockDim.x)
        g_pa32[(size_t)r*CC + c] = f2tf32(g_pa[(size_t)r*CC + c]*inv);
}

// ---------------- fp32 SGEMM (Wm1+Wm2 merged) ----------------
__global__ void __launch_bounds__(256) sgemm(
    int M, int Nn, int Kc, int S,
    const float* __restrict__ A, int lda,
    const float* __restrict__ B, const float* __restrict__ B2, int ldb,
    float* __restrict__ part)
{
    int z = blockIdx.z;
    int s = z % S, b = z / S;
    const float* Ab = A + (size_t)s*Kc;
    const float* Bb = ((b && B2) ? B2 : B) + (size_t)s*Kc*ldb;
    int m0 = blockIdx.y*128, n0 = blockIdx.x*128;
    __shared__ float As[8][128];
    __shared__ float Bs[8][128];
    int tid = threadIdx.x;
    int arow = tid >> 1, ak = (tid & 1)*4;
    int bk = tid >> 5,  bn = (tid & 31)*4;
    int tx = tid & 15,  ty = tid >> 4;
    float acc[8][8];
    #pragma unroll
    for (int i = 0; i < 8; i++)
        #pragma unroll
        for (int j = 0; j < 8; j++) acc[i][j] = 0.f;
    for (int k0 = 0; k0 < Kc; k0 += 8) {
        float4 av = make_float4(0.f,0.f,0.f,0.f);
        if (m0 + arow < M)
            av = *(const float4*)(Ab + (size_t)(m0+arow)*lda + k0 + ak);
        float4 bvv = *(const float4*)(Bb + (size_t)(k0+bk)*ldb + n0 + bn);
        __syncthreads();
        As[ak+0][arow] = av.x; As[ak+1][arow] = av.y;
        As[ak+2][arow] = av.z; As[ak+3][arow] = av.w;
        *(float4*)&Bs[bk][bn] = bvv;
        __syncthreads();
        #pragma unroll
        for (int kk = 0; kk < 8; kk++) {
            float a[8], bb[8];
            *(float4*)(a)    = *(const float4*)&As[kk][ty*8];
            *(float4*)(a+4)  = *(const float4*)&As[kk][ty*8+4];
            *(float4*)(bb)   = *(const float4*)&Bs[kk][tx*8];
            *(float4*)(bb+4) = *(const float4*)&Bs[kk][tx*8+4];
            #pragma unroll
            for (int i = 0; i < 8; i++)
                #pragma unroll
                for (int j = 0; j < 8; j++)
                    acc[i][j] += a[i]*bb[j];
        }
    }
    float* pbase = part + ((size_t)z*M)*Nn;
    #pragma unroll
    for (int i = 0; i < 8; i++) {
        int r = m0 + ty*8 + i;
        if (r < M) {
            float* prow = pbase + (size_t)r*Nn + n0 + tx*8;
            *(float4*)(prow)   = make_float4(acc[i][0],acc[i][1],acc[i][2],acc[i][3]);
            *(float4*)(prow+4) = make_float4(acc[i][4],acc[i][5],acc[i][6],acc[i][7]);
        }
    }
}

// merged Wm reduce
__global__ void k_redwm()
{
    int idx = blockIdx.x*blockDim.x + threadIdx.x;
    const int total = NN*EE*DD;
    if (idx >= total) return;
    float a = 0.f, b = 0.f;
    #pragma unroll
    for (int s = 0; s < 12; s++) {
        a += g_partm[(size_t)s*total + idx];
        b += g_partm[(size_t)(s+12)*total + idx];
    }
    g_A[idx] = a;
    g_B[idx] = b;
}

// path reduce (S=4, tf32 dual)
__global__ void reduce_ep(const float* __restrict__ part, int S, int Mtot, int Nn,
                          const float* __restrict__ bias, int dorelu, int tf32out,
                          float* __restrict__ dst1, int ld1,
                          float* __restrict__ dst2, int ld2)
{
    int idx = blockIdx.x*blockDim.x + threadIdx.x;
    if (idx >= Mtot*Nn) return;
    int r = idx / Nn, c = idx % Nn;
    float v = 0.f;
    for (int s = 0; s < S; s++)
        v += part[((size_t)s*Mtot + r)*Nn + c];
    if (bias) v += bias[c];
    if (dorelu) v = fmaxf(v, 0.f);
    if (tf32out) {
        uint32_t u = f2tf32(v);
        ((uint32_t*)dst1)[(size_t)r*ld1 + c] = u;
        if (dst2) ((uint32_t*)dst2)[(size_t)r*ld2 + c] = u;
    } else {
        dst1[(size_t)r*ld1 + c] = v;
        if (dst2) dst2[(size_t)r*ld2 + c] = v;
    }
}

// merged head/tail reduce
__global__ void reduce_ep2(const float* __restrict__ biasA, const float* __restrict__ biasB)
{
    int b = blockIdx.y;
    int idx = blockIdx.x*blockDim.x + threadIdx.x;
    if (idx >= NP*DD) return;
    int r = idx / DD, c = idx % DD;
    const float* p = g_part + (size_t)(2*b)*NP*DD;
    float v = p[(size_t)r*DD + c] + p[(size_t)NP*DD + (size_t)r*DD + c];
    v += (b ? biasB : biasA)[c];
    v = fmaxf(v, 0.f);
    (b ? g_ts : g_hs)[(size_t)r*DD + c] = v;
}

// ---------------- grouped score ----------------
__global__ void __launch_bounds__(256) k_score(const float* __restrict__ qW)
{
    extern __shared__ float sm[];
    int e = blockIdx.x, kk = blockIdx.y, n = blockIdx.z;
    int tid = threadIdx.x;
    bool strided = (kk == 1) || (kk == 3);
    bool grouph  = (kk == 0) || (kk == 3);
    for (int idx = tid; idx < EE*DD; idx += 256) {
        int v = idx / DD, d = idx % DD;
        size_t off = strided ? (((size_t)(n*EE + v)*EE + e))*DD + d
                             : (((size_t)(n*EE + e)*EE + v))*DD + d;
        sm[idx] = g_edge[off];
    }
    __syncthreads();
    int wid = tid >> 5, lane = tid & 31;
    for (int jj = wid; jj < EE-1; jj += 8) {
        int p = group_pair(n, e, jj, grouph);
        const float* qrow = qW + (size_t)p*DIM4 + kk*DD;
        float q[24];
        #pragma unroll
        for (int u = 0; u < 24; u++) q[u] = qrow[lane + 32*u];
        for (int v = 0; v < EE; v++) {
            const float* smv = sm + v*DD;
            float acc = 0.f;
            #pragma unroll
            for (int u = 0; u < 24; u++) acc += q[u]*smv[lane + 32*u];
            #pragma unroll
            for (int o = 16; o; o >>= 1) acc += __shfl_down_sync(0xffffffffu, acc, o);
            if (lane == 0) g_spart[((size_t)kk*NP + p)*EE + v] = acc;
        }
    }
}

// ---------------- softmax ----------------
__global__ void k_softmax(const int* __restrict__ hts, const float* __restrict__ battp)
{
    int p = blockIdx.x;
    int lane = threadIdx.x;
    int h = hts[p*2], t = hts[p*2+1];
    float s = -1e38f;
    if (lane < EE) {
        s = g_spart[((size_t)0*NP+p)*EE+lane] + g_spart[((size_t)1*NP+p)*EE+lane]
          + g_spart[((size_t)2*NP+p)*EE+lane] + g_spart[((size_t)3*NP+p)*EE+lane]
          + battp[0];
        if (lane == h || lane == t) s = NEGV;
    }
    float mx = s;
    #pragma unroll
    for (int o = 16; o; o >>= 1) mx = fmaxf(mx, __shfl_xor_sync(0xffffffffu, mx, o));
    float ex = (lane < EE) ? expf(s - mx) : 0.f;
    float sum = ex;
    #pragma unroll
    for (int o = 16; o; o >>= 1) sum += __shfl_xor_sync(0xffffffffu, sum, o);
    if (lane < EE) g_aw[(size_t)p*EE + lane] = ex/sum;
}

// ---------------- grouped path ----------------
__global__ void __launch_bounds__(256) k_pathg()
{
    extern __shared__ float sm[];
    float* aws = sm + EE*DD;
    int e = blockIdx.x, kk = blockIdx.y, n = blockIdx.z;
    int tid = threadIdx.x;
    bool strided = (kk == 1) || (kk == 3);
    bool grouph  = (kk == 0) || (kk == 3);
    for (int idx = tid; idx < EE*DD; idx += 256) {
        int v = idx / DD, d = idx % DD;
        size_t off = strided ? (((size_t)(n*EE + v)*EE + e))*DD + d
                             : (((size_t)(n*EE + e)*EE + v))*DD + d;
        sm[idx] = g_edge[off];
    }
    for (int idx = tid; idx < 19*EE; idx += 256) {
        int jj = idx / EE, v = idx % EE;
        int p = group_pair(n, e, jj, grouph);
        aws[idx] = g_aw[(size_t)p*EE + v];
    }
    __syncthreads();
    for (int idx = tid; idx < 19*DD; idx += 256) {
        int jj = idx / DD, d = idx % DD;
        float acc = 0.f;
        #pragma unroll
        for (int v = 0; v < EE; v++)
            acc += aws[jj*EE + v]*sm[v*DD + d];
        int p = group_pair(n, e, jj, grouph);
        g_praw32[(size_t)p*DIM4 + kk*DD + d] = f2tf32(acc);
    }
}

__global__ void k_bilred(const float* __restrict__ bbil, float* __restrict__ out)
{
    int idx = blockIdx.x*blockDim.x + threadIdx.x;
    if (idx >= NP*LL) return;
    int r = idx / LL, l = idx % LL;
    float v = bbil[l];
    #pragma unroll
    for (int k = 0; k < 24; k++)
        v += g_part[((size_t)k*NP + r)*LL + l];
    out[idx] = v;
}

// ---------------- launcher ----------------
static void* symaddr(const void* sym)
{
    void* p = nullptr;
    cudaGetSymbolAddress(&p, sym);
    return p;
}

extern "C" void kernel_launch(void* const* d_in, const int* in_sizes, int n_in,
                              void* d_out, int out_size)
{
    const float* seq   = (const float*)d_in[0];
    const float* att   = (const float*)d_in[1];
    const int*   ms    = (const int*)  d_in[2];
    const int*   hts   = (const int*)  d_in[3];
    const float* Wm1   = (const float*)d_in[4];
    const float* Wm2   = (const float*)d_in[5];
    const float* bm    = (const float*)d_in[6];
    const float* Watt  = (const float*)d_in[7];
    const float* batt  = (const float*)d_in[8];
    const float* Wpath = (const float*)d_in[9];
    const float* bpath = (const float*)d_in[10];
    const float* Whead = (const float*)d_in[11];
    const float* bhead = (const float*)d_in[12];
    const float* Wtail = (const float*)d_in[13];
    const float* btail = (const float*)d_in[14];
    const float* Wbil  = (const float*)d_in[15];
    const float* bbil  = (const float*)d_in[16];
    float* out = (float*)d_out;

    float*    glob   = (float*)symaddr(g_glob);
    float*    qW     = (float*)symaddr(g_qW);
    float*    part   = (float*)symaddr(g_part);
    float*    partm  = (float*)symaddr(g_partm);
    uint32_t* pa32   = (uint32_t*)symaddr(g_pa32);
    uint32_t* seqT32 = (uint32_t*)symaddr(g_seqT32);
    uint32_t* q32    = (uint32_t*)symaddr(g_q32);
    uint32_t* hcat32 = (uint32_t*)symaddr(g_hcat32);
    uint32_t* tcat32 = (uint32_t*)symaddr(g_tcat32);
    uint32_t* praw32 = (uint32_t*)symaddr(g_praw32);
    uint32_t* wTatt  = (uint32_t*)symaddr(g_wT_att32);
    uint32_t* wTpath = (uint32_t*)symaddr(g_wT_path32);
    uint32_t* wThead = (uint32_t*)symaddr(g_wT_head32);
    uint32_t* wTtail = (uint32_t*)symaddr(g_wT_tail32);
    uint32_t* wTbil  = (uint32_t*)symaddr(g_wT_bil32);

    const int SMEM_WG = 98304;
    const int SMEM_WB = 98304;
    const int SMEM_SC = EE*DD*4;
    const int SMEM_PG = EE*DD*4 + 19*EE*4;
    cudaFuncSetAttribute(wgemm,  cudaFuncAttributeMaxDynamicSharedMemorySize, SMEM_WG);
    cudaFuncSetAttribute(wbil,   cudaFuncAttributeMaxDynamicSharedMemorySize, SMEM_WB);
    cudaFuncSetAttribute(k_score, cudaFuncAttributeMaxDynamicSharedMemorySize, SMEM_SC);
    cudaFuncSetAttribute(k_pathg, cudaFuncAttributeMaxDynamicSharedMemorySize, SMEM_PG);

    // one-time stream/event creation (first call is the uncaptured correctness run;
    // the same handles are reused identically on every call — identical work per call)
    static cudaStream_t s1 = nullptr, s2 = nullptr;
    static cudaEvent_t ev0, evG, evT, evE;
    if (!s1) {
        cudaStreamCreateWithFlags(&s1, cudaStreamNonBlocking);
        cudaStreamCreateWithFlags(&s2, cudaStreamNonBlocking);
        cudaEventCreateWithFlags(&ev0, cudaEventDisableTiming);
        cudaEventCreateWithFlags(&evG, cudaEventDisableTiming);
        cudaEventCreateWithFlags(&evT, cudaEventDisableTiming);
        cudaEventCreateWithFlags(&evE, cudaEventDisableTiming);
    }

    // fork point on origin stream
    cudaEventRecord(ev0, 0);
    cudaStreamWaitEvent(s2, ev0, 0);

    // s2: all transposes (independent of everything else)
    ktransAll<<<16512, dim3(32,8), 0, s2>>>(Watt, Wpath, Whead, Wtail, Wbil,
                                            wTatt, wTpath, wThead, wTtail, wTbil);
    ktransB<<<dim3(DD/32, CC/32, NN), dim3(32,8), 0, s2>>>(seq, seqT32);
    cudaEventRecord(evT, s2);

    // origin: gather
    k_gatherm<<<NN*EE*MMENT, 256>>>(seq, att, ms);
    cudaEventRecord(evG, 0);

    // s1: lse -> Wm sgemm -> reduce -> edge (only k_score/k_pathg consume edge)
    cudaStreamWaitEvent(s1, evG, 0);
    k_lse<<<NN*EE, 256, 0, s1>>>();
    sgemm<<<dim3(6,1,24), 256, 0, s1>>>(NN*EE, DD, 64, 12, glob, DD, Wm1, Wm2, DD, partm);
    k_redwm<<<(NN*EE*DD+255)/256, 256, 0, s1>>>();
    k_edge<<<(NN*EE*EE*DD+255)/256, 256, 0, s1>>>(bm);
    cudaEventRecord(evE, s1);

    // origin: pair (needs gatherm) overlaps s1/s2
    k_pair<<<NP, 256>>>(hts, ms);

    // join transposes before first wgemm
    cudaStreamWaitEvent(0, evT, 0);

    // qW = q @ Watt (tf32 mma)
    wgemm<<<dim3(24,12,1), 256, SMEM_WG>>>(NP, 48, 1,
        q32, DIM2, 0, wTatt, DIM2, 0, nullptr, nullptr,
        qW, DIM4, 0, nullptr, nullptr, 0, 0,
        nullptr, nullptr, 0, 0, nullptr, 0, 0);

    // rs = pa @ seq (tf32 mma, per-doc batch, direct dual tf32 epilogue)
    wgemm<<<dim3(6,3,NN), 256, SMEM_WG>>>(PP, 16, 1,
        pa32, CC, (long long)PP*CC, seqT32, CC, (long long)DD*CC, nullptr, nullptr,
        (float*)(hcat32 + DD), DIM3, (long long)PP*DIM3, nullptr,
        (float*)(tcat32 + DD), DIM3, (long long)PP*DIM3,
        nullptr, nullptr, 0, 1, nullptr, 0, 0);

    // join edge chain before score
    cudaStreamWaitEvent(0, evE, 0);

    // grouped score -> softmax -> grouped path
    k_score<<<dim3(EE,4,NN), 256, SMEM_SC>>>(qW);
    k_softmax<<<NP, 32>>>(hts, batt);
    k_pathg<<<dim3(EE,4,NN), 256, SMEM_PG>>>();

    // path = relu(pathraw @ Wpath + bpath): Sr=4 -> 288 CTAs
    wgemm<<<dim3(6,12,4), 256, SMEM_WG>>>(NP, 24, 4,
        praw32, DIM4, 0, wTpath, DIM4, 0, nullptr, nullptr,
        nullptr, 0, 0, nullptr, nullptr, 0, 0,
        nullptr, nullptr, 0, 0, part, NP, DD);
    reduce_ep<<<(NP*DD+255)/256, 256>>>(part, 4, NP, DD, bpath, 1, 1,
                                        (float*)(hcat32 + 2*DD), DIM3,
                                        (float*)(tcat32 + 2*DD), DIM3);

    // hs / ts projections: merged batch + Sr=2 partials, merged reduce
    wgemm<<<dim3(6,12,4), 256, SMEM_WG>>>(NP, 36, 2,
        hcat32, DIM3, 0, wThead, DIM3, 0, tcat32, wTtail,
        nullptr, 0, 0, nullptr, nullptr, 0, 0,
        nullptr, nullptr, 0, 0, part, NP, DD);
    reduce_ep2<<<dim3((NP*DD+255)/256, 2), 256>>>(bhead, btail);

    // bilinear head
    wbil<<<dim3(12,24), 256, SMEM_WB>>>(wTbil);
    k_bilred<<<(NP*LL+255)/256, 256>>>(bbil, out);
}